// round 1
// baseline (speedup 1.0000x reference)
#include <cuda_runtime.h>
#include <math.h>

// Problem constants
#define B_ 2
#define S_ 2048
#define D_ 1024
#define H_ 16
#define HD_ 64
#define M_ (B_ * S_)   // 4096 rows for the projection GEMMs

// Scratch (device globals; no allocations allowed)
__device__ float g_q[B_ * S_ * D_];
__device__ float g_k[B_ * S_ * D_];
__device__ float g_v[B_ * S_ * D_];
__device__ float g_attn[B_ * S_ * D_];

// ---------------------------------------------------------------------------
// SGEMM: C[M,N] = A[M,K] @ B[K,N], all row-major, fp32.
// 128x128 block tile, BK=8, 8x8 per thread, 256 threads.
// M,N divisible by 128; K divisible by 8 (true for all our shapes).
// ---------------------------------------------------------------------------
__global__ __launch_bounds__(256) void sgemm128(const float* __restrict__ A,
                                                const float* __restrict__ B,
                                                float* __restrict__ C,
                                                int M, int N, int K) {
    __shared__ float As[8][128];   // transposed A tile
    __shared__ float Bs[8][128];

    const int tid = threadIdx.x;
    const int tx = tid & 15;        // 0..15 -> N direction
    const int ty = tid >> 4;        // 0..15 -> M direction
    const int bm = blockIdx.y * 128;
    const int bn = blockIdx.x * 128;

    const int aRow = tid >> 1;          // 0..127
    const int aCol = (tid & 1) * 4;     // 0 or 4
    const int bRow = tid >> 5;          // 0..7
    const int bCol = (tid & 31) * 4;    // 0..124

    float acc[8][8];
#pragma unroll
    for (int i = 0; i < 8; i++)
#pragma unroll
        for (int j = 0; j < 8; j++) acc[i][j] = 0.f;

    const float* Aptr = A + (long)(bm + aRow) * K + aCol;
    const float* Bptr = B + (long)bRow * N + bn + bCol;

    for (int kt = 0; kt < K; kt += 8) {
        float4 av = *(const float4*)(Aptr + kt);
        As[aCol + 0][aRow] = av.x;
        As[aCol + 1][aRow] = av.y;
        As[aCol + 2][aRow] = av.z;
        As[aCol + 3][aRow] = av.w;
        float4 bv = *(const float4*)(Bptr + (long)kt * N);
        *(float4*)&Bs[bRow][bCol] = bv;
        __syncthreads();

#pragma unroll
        for (int kk = 0; kk < 8; kk++) {
            float a[8], b[8];
#pragma unroll
            for (int i = 0; i < 8; i++) a[i] = As[kk][ty * 8 + i];
#pragma unroll
            for (int j = 0; j < 8; j++) b[j] = Bs[kk][tx * 8 + j];
#pragma unroll
            for (int i = 0; i < 8; i++)
#pragma unroll
                for (int j = 0; j < 8; j++) acc[i][j] = fmaf(a[i], b[j], acc[i][j]);
        }
        __syncthreads();
    }

#pragma unroll
    for (int i = 0; i < 8; i++) {
        float* Crow = C + (long)(bm + ty * 8 + i) * N + bn + tx * 8;
        *(float4*)(Crow)     = make_float4(acc[i][0], acc[i][1], acc[i][2], acc[i][3]);
        *(float4*)(Crow + 4) = make_float4(acc[i][4], acc[i][5], acc[i][6], acc[i][7]);
    }
}

// ---------------------------------------------------------------------------
// RoPE applied in-place to q and k, layout [B*S, D] with n = h*64 + d.
// Pairs are (2p, 2p+1) within each head dim; freqs are [S, 32].
// ---------------------------------------------------------------------------
__global__ void rope_kernel(float* __restrict__ q, float* __restrict__ k,
                            const float* __restrict__ fc,
                            const float* __restrict__ fs) {
    int t = blockIdx.x * blockDim.x + threadIdx.x;
    const int total = B_ * S_ * H_ * (HD_ / 2);  // 2,097,152
    if (t >= total) return;
    int p = t & 31;               // pair index 0..31
    int h = (t >> 5) & 15;        // head
    int bs = t >> 9;              // b*S + s, 0..4095
    int s = bs & (S_ - 1);
    float c = fc[s * 32 + p];
    float sn = fs[s * 32 + p];
    long base = (long)bs * D_ + h * HD_ + 2 * p;
    float2 qv = *(float2*)(q + base);
    *(float2*)(q + base) = make_float2(qv.x * c - qv.y * sn, qv.x * sn + qv.y * c);
    float2 kv = *(float2*)(k + base);
    *(float2*)(k + base) = make_float2(kv.x * c - kv.y * sn, kv.x * sn + kv.y * c);
}

// ---------------------------------------------------------------------------
// Flash attention, causal, fp32. Br = Bc = 64, HD = 64.
// Grid: (S/64 = 32 query tiles, B*H = 32). 256 threads (16x16 thread tile),
// each thread owns a 4x4 patch of S and of O.
// q,k,v,o layout: [B*S, D] with columns h*64+d (so output is GEMM-ready).
// ---------------------------------------------------------------------------
#define FP 65   // padded row stride for 64-wide SMEM tiles

__global__ __launch_bounds__(256) void flash_kernel(const float* __restrict__ q,
                                                    const float* __restrict__ k,
                                                    const float* __restrict__ v,
                                                    float* __restrict__ o) {
    extern __shared__ float sm[];
    float* Qs  = sm;                 // [64][65]
    float* Ks  = Qs + 64 * FP;       // [64][65]
    float* Vs  = Ks + 64 * FP;       // [64][65]
    float* Ps  = Vs + 64 * FP;       // [64][65] scores / probs
    float* mrow = Ps + 64 * FP;      // [64]
    float* lrow = mrow + 64;         // [64]
    float* arow = lrow + 64;         // [64]
    float* red  = arow + 64;         // [64][4]

    const int tid = threadIdx.x;
    const int tx = tid & 15;     // 0..15 (cols)
    const int ty = tid >> 4;     // 0..15 (rows)
    const int qt = blockIdx.x;   // query tile
    const int bh = blockIdx.y;   // b*H + h
    const int q0 = qt * 64;
    const float scale = 0.125f;  // 1/sqrt(64)

    const long headoff = (long)(bh >> 4) * S_ * D_ + (bh & 15) * HD_;
    const float* qb = q + headoff;
    const float* kb = k + headoff;
    const float* vb = v + headoff;
    float* ob = o + headoff;

    // Load Q tile (64 rows x 64 cols)
    for (int i = tid; i < 1024; i += 256) {
        int r = i >> 4;
        int c = (i & 15) << 2;
        float4 u = *(const float4*)(qb + (long)(q0 + r) * D_ + c);
        float* dst = Qs + r * FP + c;
        dst[0] = u.x; dst[1] = u.y; dst[2] = u.z; dst[3] = u.w;
    }
    if (tid < 64) { mrow[tid] = -1e30f; lrow[tid] = 0.f; }

    float oacc[4][4];
#pragma unroll
    for (int i = 0; i < 4; i++)
#pragma unroll
        for (int j = 0; j < 4; j++) oacc[i][j] = 0.f;

    const int row = tid >> 2;   // 0..63 (softmax row)
    const int seg = tid & 3;    // 0..3  (16-col segment)

    for (int jt = 0; jt <= qt; jt++) {
        const int k0 = jt * 64;
        // Load K and V tiles
        for (int i = tid; i < 1024; i += 256) {
            int r = i >> 4;
            int c = (i & 15) << 2;
            const long goff = (long)(k0 + r) * D_ + c;
            float4 u = *(const float4*)(kb + goff);
            float* dk = Ks + r * FP + c;
            dk[0] = u.x; dk[1] = u.y; dk[2] = u.z; dk[3] = u.w;
            float4 w = *(const float4*)(vb + goff);
            float* dv = Vs + r * FP + c;
            dv[0] = w.x; dv[1] = w.y; dv[2] = w.z; dv[3] = w.w;
        }
        __syncthreads();

        // S = Q @ K^T  (each thread 4x4)
        float sacc[4][4];
#pragma unroll
        for (int i = 0; i < 4; i++)
#pragma unroll
            for (int j = 0; j < 4; j++) sacc[i][j] = 0.f;

        for (int d = 0; d < 64; d++) {
            float qf[4], kf[4];
#pragma unroll
            for (int ii = 0; ii < 4; ii++) qf[ii] = Qs[(ty * 4 + ii) * FP + d];
#pragma unroll
            for (int jj = 0; jj < 4; jj++) kf[jj] = Ks[(tx * 4 + jj) * FP + d];
#pragma unroll
            for (int ii = 0; ii < 4; ii++)
#pragma unroll
                for (int jj = 0; jj < 4; jj++)
                    sacc[ii][jj] = fmaf(qf[ii], kf[jj], sacc[ii][jj]);
        }

        const bool diag = (jt == qt);
#pragma unroll
        for (int ii = 0; ii < 4; ii++) {
#pragma unroll
            for (int jj = 0; jj < 4; jj++) {
                float sv = sacc[ii][jj] * scale;
                if (diag && (k0 + tx * 4 + jj) > (q0 + ty * 4 + ii)) sv = -1e30f;
                Ps[(ty * 4 + ii) * FP + tx * 4 + jj] = sv;
            }
        }
        __syncthreads();

        // Online softmax: 4 threads per row, 16 cols each
        float* prow = Ps + row * FP + seg * 16;
        float pm = -1e30f;
#pragma unroll
        for (int c = 0; c < 16; c++) pm = fmaxf(pm, prow[c]);
        red[(row << 2) + seg] = pm;
        __syncthreads();
        if (seg == 0) {
            float tm = fmaxf(fmaxf(red[row * 4], red[row * 4 + 1]),
                             fmaxf(red[row * 4 + 2], red[row * 4 + 3]));
            float mold = mrow[row];
            float mnew = fmaxf(mold, tm);
            arow[row] = __expf(mold - mnew);
            mrow[row] = mnew;
        }
        __syncthreads();
        {
            float mnew = mrow[row];
            float psum = 0.f;
#pragma unroll
            for (int c = 0; c < 16; c++) {
                float e = __expf(prow[c] - mnew);
                prow[c] = e;
                psum += e;
            }
            red[(row << 2) + seg] = psum;
        }
        __syncthreads();
        if (seg == 0) {
            lrow[row] = lrow[row] * arow[row] +
                        (red[row * 4] + red[row * 4 + 1] + red[row * 4 + 2] + red[row * 4 + 3]);
        }

        // O = O * alpha + P @ V
        float al[4];
#pragma unroll
        for (int ii = 0; ii < 4; ii++) al[ii] = arow[ty * 4 + ii];
#pragma unroll
        for (int ii = 0; ii < 4; ii++)
#pragma unroll
            for (int dd = 0; dd < 4; dd++) oacc[ii][dd] *= al[ii];

        for (int j = 0; j < 64; j++) {
            float vf[4];
#pragma unroll
            for (int dd = 0; dd < 4; dd++) vf[dd] = Vs[j * FP + tx * 4 + dd];
#pragma unroll
            for (int ii = 0; ii < 4; ii++) {
                float p = Ps[(ty * 4 + ii) * FP + j];
#pragma unroll
                for (int dd = 0; dd < 4; dd++)
                    oacc[ii][dd] = fmaf(p, vf[dd], oacc[ii][dd]);
            }
        }
        __syncthreads();   // protect Ks/Vs/Ps before next tile load
    }

    // Normalize and write out
#pragma unroll
    for (int ii = 0; ii < 4; ii++) {
        float inv = 1.f / lrow[ty * 4 + ii];
        float* orow = ob + (long)(q0 + ty * 4 + ii) * D_ + tx * 4;
        *(float4*)orow = make_float4(oacc[ii][0] * inv, oacc[ii][1] * inv,
                                     oacc[ii][2] * inv, oacc[ii][3] * inv);
    }
}

// ---------------------------------------------------------------------------
// Launch
// ---------------------------------------------------------------------------
extern "C" void kernel_launch(void* const* d_in, const int* in_sizes, int n_in,
                              void* d_out, int out_size) {
    const float* x  = (const float*)d_in[0];
    const float* wq = (const float*)d_in[1];
    const float* wk = (const float*)d_in[2];
    const float* wv = (const float*)d_in[3];
    const float* wo = (const float*)d_in[4];
    const float* fc = (const float*)d_in[5];
    const float* fs = (const float*)d_in[6];
    // d_in[7] (mask) and d_in[8] (start_pos) unused: causal mask is implicit.
    float* out = (float*)d_out;

    float *q, *k, *v, *attn;
    cudaGetSymbolAddress((void**)&q, g_q);
    cudaGetSymbolAddress((void**)&k, g_k);
    cudaGetSymbolAddress((void**)&v, g_v);
    cudaGetSymbolAddress((void**)&attn, g_attn);

    dim3 ggrid(D_ / 128, M_ / 128);   // (8, 32)
    sgemm128<<<ggrid, 256>>>(x, wq, q, M_, D_, D_);
    sgemm128<<<ggrid, 256>>>(x, wk, k, M_, D_, D_);
    sgemm128<<<ggrid, 256>>>(x, wv, v, M_, D_, D_);

    const int rope_total = B_ * S_ * H_ * (HD_ / 2);
    rope_kernel<<<(rope_total + 255) / 256, 256>>>(q, k, fc, fs);

    size_t fsm = (size_t)(4 * 64 * FP + 3 * 64 + 256) * sizeof(float);
    cudaFuncSetAttribute(flash_kernel, cudaFuncAttributeMaxDynamicSharedMemorySize, (int)fsm);
    flash_kernel<<<dim3(S_ / 64, B_ * H_), 256, fsm>>>(q, k, v, attn);

    sgemm128<<<ggrid, 256>>>(attn, wo, out, M_, D_, D_);
}

// round 4
// speedup vs baseline: 1.2258x; 1.2258x over previous
#include <cuda_runtime.h>
#include <cuda_bf16.h>
#include <stdint.h>
#include <math.h>

// Problem constants
#define B_ 2
#define S_ 2048
#define D_ 1024
#define H_ 16
#define HD_ 64
#define M_ (B_ * S_)

// Scratch (device globals; no allocations allowed)
__device__ float g_q[B_ * S_ * D_];
__device__ float g_k[B_ * S_ * D_];
__device__ float g_v[B_ * S_ * D_];
__device__ float g_attn[B_ * S_ * D_];

// ---------------------------------------------------------------------------
// bf16-split (3-term) tensor-core GEMM: C = A @ B, row-major fp32 in/out.
// Each fp32 operand split as hi + lo (bf16 each); C += hi*hi + hi*lo + lo*hi.
// 128x128x16 block tile, 8 warps (2x4), 64x32 warp tile, m16n8k16 bf16 mma.
// cp.async double-buffered fp32 SMEM tiles; conversion in registers.
// ---------------------------------------------------------------------------
#define BM 128
#define BN 128
#define BKT 16
#define AST 20    // As row stride (floats)
#define BST 132   // Bs row stride (floats)

__device__ __forceinline__ void cp_async16(unsigned int dst, const void* src) {
    asm volatile("cp.async.cg.shared.global [%0], [%1], 16;\n" :: "r"(dst), "l"(src));
}
__device__ __forceinline__ void cp_commit() {
    asm volatile("cp.async.commit_group;\n" ::: "memory");
}
template <int N>
__device__ __forceinline__ void cp_wait() {
    asm volatile("cp.async.wait_group %0;\n" :: "n"(N) : "memory");
}

// Split two fp32 into packed bf16x2 hi and lo (low 16 bits = first element).
__device__ __forceinline__ void split2(float x, float y,
                                       unsigned int& hi, unsigned int& lo) {
    __nv_bfloat16 hx = __float2bfloat16_rn(x);
    __nv_bfloat16 hy = __float2bfloat16_rn(y);
    float rx = x - __bfloat162float(hx);
    float ry = y - __bfloat162float(hy);
    __nv_bfloat16 lx = __float2bfloat16_rn(rx);
    __nv_bfloat16 ly = __float2bfloat16_rn(ry);
    unsigned short hxu = *(unsigned short*)&hx;
    unsigned short hyu = *(unsigned short*)&hy;
    unsigned short lxu = *(unsigned short*)&lx;
    unsigned short lyu = *(unsigned short*)&ly;
    hi = (unsigned int)hxu | ((unsigned int)hyu << 16);
    lo = (unsigned int)lxu | ((unsigned int)lyu << 16);
}

__device__ __forceinline__ void mma_bf16(float* c, const unsigned int* a,
                                         const unsigned int* b) {
    asm volatile(
        "mma.sync.aligned.m16n8k16.row.col.f32.bf16.bf16.f32 "
        "{%0,%1,%2,%3}, {%4,%5,%6,%7}, {%8,%9}, {%0,%1,%2,%3};\n"
        : "+f"(c[0]), "+f"(c[1]), "+f"(c[2]), "+f"(c[3])
        : "r"(a[0]), "r"(a[1]), "r"(a[2]), "r"(a[3]),
          "r"(b[0]), "r"(b[1]));
}

__global__ __launch_bounds__(256) void gemm_bf16x3(const float* __restrict__ A,
                                                   const float* __restrict__ B,
                                                   float* __restrict__ C,
                                                   int M, int N, int K) {
    __shared__ float As[2][BM * AST];
    __shared__ float Bs[2][BKT * BST];

    const int tid = threadIdx.x;
    const int bm = blockIdx.y * BM;
    const int bn = blockIdx.x * BN;

    const int wid = tid >> 5;
    const int lane = tid & 31;
    const int wm = (wid >> 2) * 64;   // 0 or 64
    const int wn = (wid & 3) * 32;    // 0,32,64,96
    const int g = lane >> 2;          // 0..7
    const int t4 = lane & 3;          // 0..3

    const int aRow0 = tid >> 2;
    const int aC40  = tid & 3;
    const int aRow1 = aRow0 + 64;
    const int bRow0 = tid >> 5;
    const int bC40  = tid & 31;
    const int bRow1 = bRow0 + 8;

    const unsigned int sA = (unsigned int)__cvta_generic_to_shared(&As[0][0]);
    const unsigned int sB = (unsigned int)__cvta_generic_to_shared(&Bs[0][0]);
    const unsigned int stageA = BM * AST * 4;
    const unsigned int stageB = BKT * BST * 4;

    float cc[4][4][4];
#pragma unroll
    for (int i = 0; i < 4; i++)
#pragma unroll
        for (int j = 0; j < 4; j++)
#pragma unroll
            for (int r = 0; r < 4; r++) cc[i][j][r] = 0.f;

    const int Kt = K / BKT;

    auto issue_stage = [&](int kt, int buf) {
        const float* Ag0 = A + (long)(bm + aRow0) * K + kt * BKT + aC40 * 4;
        cp_async16(sA + buf * stageA + (unsigned)(aRow0 * AST + aC40 * 4) * 4, Ag0);
        const float* Ag1 = A + (long)(bm + aRow1) * K + kt * BKT + aC40 * 4;
        cp_async16(sA + buf * stageA + (unsigned)(aRow1 * AST + aC40 * 4) * 4, Ag1);
        const float* Bg0 = B + (long)(kt * BKT + bRow0) * N + bn + bC40 * 4;
        cp_async16(sB + buf * stageB + (unsigned)(bRow0 * BST + bC40 * 4) * 4, Bg0);
        const float* Bg1 = B + (long)(kt * BKT + bRow1) * N + bn + bC40 * 4;
        cp_async16(sB + buf * stageB + (unsigned)(bRow1 * BST + bC40 * 4) * 4, Bg1);
        cp_commit();
    };

    issue_stage(0, 0);

    for (int kt = 0; kt < Kt; kt++) {
        const int buf = kt & 1;
        if (kt + 1 < Kt) {
            issue_stage(kt + 1, buf ^ 1);
            cp_wait<1>();
        } else {
            cp_wait<0>();
        }
        __syncthreads();

        const float* Asb = &As[buf][0];
        const float* Bsb = &Bs[buf][0];

        // A fragments (m16n8k16): per mt, 4 regs x {hi, lo}
        unsigned int ah[4][4], al[4][4];
#pragma unroll
        for (int mt = 0; mt < 4; mt++) {
            const int r0 = wm + mt * 16;
            float2 u0 = *(const float2*)&Asb[(r0 + g) * AST + 2 * t4];
            float2 u1 = *(const float2*)&Asb[(r0 + g + 8) * AST + 2 * t4];
            float2 u2 = *(const float2*)&Asb[(r0 + g) * AST + 2 * t4 + 8];
            float2 u3 = *(const float2*)&Asb[(r0 + g + 8) * AST + 2 * t4 + 8];
            split2(u0.x, u0.y, ah[mt][0], al[mt][0]);
            split2(u1.x, u1.y, ah[mt][1], al[mt][1]);
            split2(u2.x, u2.y, ah[mt][2], al[mt][2]);
            split2(u3.x, u3.y, ah[mt][3], al[mt][3]);
        }
        // B fragments: per nt, 2 regs x {hi, lo}; B[k][n], k pairs from rows
        unsigned int bh[4][2], bl[4][2];
#pragma unroll
        for (int nt = 0; nt < 4; nt++) {
            const int c0 = wn + nt * 8 + g;
            float x0 = Bsb[(2 * t4) * BST + c0];
            float y0 = Bsb[(2 * t4 + 1) * BST + c0];
            float x1 = Bsb[(2 * t4 + 8) * BST + c0];
            float y1 = Bsb[(2 * t4 + 9) * BST + c0];
            split2(x0, y0, bh[nt][0], bl[nt][0]);
            split2(x1, y1, bh[nt][1], bl[nt][1]);
        }

#pragma unroll
        for (int mt = 0; mt < 4; mt++) {
#pragma unroll
            for (int nt = 0; nt < 4; nt++) {
                mma_bf16(cc[mt][nt], ah[mt], bl[nt]);   // hi*lo
                mma_bf16(cc[mt][nt], al[mt], bh[nt]);   // lo*hi
                mma_bf16(cc[mt][nt], ah[mt], bh[nt]);   // hi*hi
            }
        }
        __syncthreads();
    }

    // Epilogue: c0:(g,2t4) c1:(g,2t4+1) c2:(g+8,2t4) c3:(g+8,2t4+1)
#pragma unroll
    for (int mt = 0; mt < 4; mt++) {
#pragma unroll
        for (int nt = 0; nt < 4; nt++) {
            const int row = bm + wm + mt * 16 + g;
            const int col = bn + wn + nt * 8 + 2 * t4;
            *(float2*)(C + (long)row * N + col) =
                make_float2(cc[mt][nt][0], cc[mt][nt][1]);
            *(float2*)(C + (long)(row + 8) * N + col) =
                make_float2(cc[mt][nt][2], cc[mt][nt][3]);
        }
    }
}

// ---------------------------------------------------------------------------
// RoPE applied in-place to q and k, layout [B*S, D] with n = h*64 + d.
// ---------------------------------------------------------------------------
__global__ void rope_kernel(float* __restrict__ q, float* __restrict__ k,
                            const float* __restrict__ fc,
                            const float* __restrict__ fs) {
    int t = blockIdx.x * blockDim.x + threadIdx.x;
    const int total = B_ * S_ * H_ * (HD_ / 2);
    if (t >= total) return;
    int p = t & 31;
    int h = (t >> 5) & 15;
    int bs = t >> 9;
    int s = bs & (S_ - 1);
    float c = fc[s * 32 + p];
    float sn = fs[s * 32 + p];
    long base = (long)bs * D_ + h * HD_ + 2 * p;
    float2 qv = *(float2*)(q + base);
    *(float2*)(q + base) = make_float2(qv.x * c - qv.y * sn, qv.x * sn + qv.y * c);
    float2 kv = *(float2*)(k + base);
    *(float2*)(k + base) = make_float2(kv.x * c - kv.y * sn, kv.x * sn + kv.y * c);
}

// ---------------------------------------------------------------------------
// Flash attention, causal, fp32. Br = Bc = 64, HD = 64. (unchanged, known good)
// ---------------------------------------------------------------------------
#define FP 65

__global__ __launch_bounds__(256) void flash_kernel(const float* __restrict__ q,
                                                    const float* __restrict__ k,
                                                    const float* __restrict__ v,
                                                    float* __restrict__ o) {
    extern __shared__ float sm[];
    float* Qs  = sm;
    float* Ks  = Qs + 64 * FP;
    float* Vs  = Ks + 64 * FP;
    float* Ps  = Vs + 64 * FP;
    float* mrow = Ps + 64 * FP;
    float* lrow = mrow + 64;
    float* arow = lrow + 64;
    float* red  = arow + 64;

    const int tid = threadIdx.x;
    const int tx = tid & 15;
    const int ty = tid >> 4;
    const int qt = blockIdx.x;
    const int bh = blockIdx.y;
    const int q0 = qt * 64;
    const float scale = 0.125f;

    const long headoff = (long)(bh >> 4) * S_ * D_ + (bh & 15) * HD_;
    const float* qb = q + headoff;
    const float* kb = k + headoff;
    const float* vb = v + headoff;
    float* ob = o + headoff;

    for (int i = tid; i < 1024; i += 256) {
        int r = i >> 4;
        int c = (i & 15) << 2;
        float4 u = *(const float4*)(qb + (long)(q0 + r) * D_ + c);
        float* dst = Qs + r * FP + c;
        dst[0] = u.x; dst[1] = u.y; dst[2] = u.z; dst[3] = u.w;
    }
    if (tid < 64) { mrow[tid] = -1e30f; lrow[tid] = 0.f; }

    float oacc[4][4];
#pragma unroll
    for (int i = 0; i < 4; i++)
#pragma unroll
        for (int j = 0; j < 4; j++) oacc[i][j] = 0.f;

    const int row = tid >> 2;
    const int seg = tid & 3;

    for (int jt = 0; jt <= qt; jt++) {
        const int k0 = jt * 64;
        for (int i = tid; i < 1024; i += 256) {
            int r = i >> 4;
            int c = (i & 15) << 2;
            const long goff = (long)(k0 + r) * D_ + c;
            float4 u = *(const float4*)(kb + goff);
            float* dk = Ks + r * FP + c;
            dk[0] = u.x; dk[1] = u.y; dk[2] = u.z; dk[3] = u.w;
            float4 w = *(const float4*)(vb + goff);
            float* dv = Vs + r * FP + c;
            dv[0] = w.x; dv[1] = w.y; dv[2] = w.z; dv[3] = w.w;
        }
        __syncthreads();

        float sacc[4][4];
#pragma unroll
        for (int i = 0; i < 4; i++)
#pragma unroll
            for (int j = 0; j < 4; j++) sacc[i][j] = 0.f;

        for (int d = 0; d < 64; d++) {
            float qf[4], kf[4];
#pragma unroll
            for (int ii = 0; ii < 4; ii++) qf[ii] = Qs[(ty * 4 + ii) * FP + d];
#pragma unroll
            for (int jj = 0; jj < 4; jj++) kf[jj] = Ks[(tx * 4 + jj) * FP + d];
#pragma unroll
            for (int ii = 0; ii < 4; ii++)
#pragma unroll
                for (int jj = 0; jj < 4; jj++)
                    sacc[ii][jj] = fmaf(qf[ii], kf[jj], sacc[ii][jj]);
        }

        const bool diag = (jt == qt);
#pragma unroll
        for (int ii = 0; ii < 4; ii++) {
#pragma unroll
            for (int jj = 0; jj < 4; jj++) {
                float sv = sacc[ii][jj] * scale;
                if (diag && (k0 + tx * 4 + jj) > (q0 + ty * 4 + ii)) sv = -1e30f;
                Ps[(ty * 4 + ii) * FP + tx * 4 + jj] = sv;
            }
        }
        __syncthreads();

        float* prow = Ps + row * FP + seg * 16;
        float pm = -1e30f;
#pragma unroll
        for (int c = 0; c < 16; c++) pm = fmaxf(pm, prow[c]);
        red[(row << 2) + seg] = pm;
        __syncthreads();
        if (seg == 0) {
            float tm = fmaxf(fmaxf(red[row * 4], red[row * 4 + 1]),
                             fmaxf(red[row * 4 + 2], red[row * 4 + 3]));
            float mold = mrow[row];
            float mnew = fmaxf(mold, tm);
            arow[row] = __expf(mold - mnew);
            mrow[row] = mnew;
        }
        __syncthreads();
        {
            float mnew = mrow[row];
            float psum = 0.f;
#pragma unroll
            for (int c = 0; c < 16; c++) {
                float e = __expf(prow[c] - mnew);
                prow[c] = e;
                psum += e;
            }
            red[(row << 2) + seg] = psum;
        }
        __syncthreads();
        if (seg == 0) {
            lrow[row] = lrow[row] * arow[row] +
                        (red[row * 4] + red[row * 4 + 1] + red[row * 4 + 2] + red[row * 4 + 3]);
        }

        float al[4];
#pragma unroll
        for (int ii = 0; ii < 4; ii++) al[ii] = arow[ty * 4 + ii];
#pragma unroll
        for (int ii = 0; ii < 4; ii++)
#pragma unroll
            for (int dd = 0; dd < 4; dd++) oacc[ii][dd] *= al[ii];

        for (int j = 0; j < 64; j++) {
            float vf[4];
#pragma unroll
            for (int dd = 0; dd < 4; dd++) vf[dd] = Vs[j * FP + tx * 4 + dd];
#pragma unroll
            for (int ii = 0; ii < 4; ii++) {
                float p = Ps[(ty * 4 + ii) * FP + j];
#pragma unroll
                for (int dd = 0; dd < 4; dd++)
                    oacc[ii][dd] = fmaf(p, vf[dd], oacc[ii][dd]);
            }
        }
        __syncthreads();
    }

#pragma unroll
    for (int ii = 0; ii < 4; ii++) {
        float inv = 1.f / lrow[ty * 4 + ii];
        float* orow = ob + (long)(q0 + ty * 4 + ii) * D_ + tx * 4;
        *(float4*)orow = make_float4(oacc[ii][0] * inv, oacc[ii][1] * inv,
                                     oacc[ii][2] * inv, oacc[ii][3] * inv);
    }
}

// ---------------------------------------------------------------------------
// Launch
// ---------------------------------------------------------------------------
extern "C" void kernel_launch(void* const* d_in, const int* in_sizes, int n_in,
                              void* d_out, int out_size) {
    const float* x  = (const float*)d_in[0];
    const float* wq = (const float*)d_in[1];
    const float* wk = (const float*)d_in[2];
    const float* wv = (const float*)d_in[3];
    const float* wo = (const float*)d_in[4];
    const float* fc = (const float*)d_in[5];
    const float* fs = (const float*)d_in[6];
    float* out = (float*)d_out;

    float *q, *k, *v, *attn;
    cudaGetSymbolAddress((void**)&q, g_q);
    cudaGetSymbolAddress((void**)&k, g_k);
    cudaGetSymbolAddress((void**)&v, g_v);
    cudaGetSymbolAddress((void**)&attn, g_attn);

    dim3 ggrid(D_ / BN, M_ / BM);   // (8, 32)
    gemm_bf16x3<<<ggrid, 256>>>(x, wq, q, M_, D_, D_);
    gemm_bf16x3<<<ggrid, 256>>>(x, wk, k, M_, D_, D_);
    gemm_bf16x3<<<ggrid, 256>>>(x, wv, v, M_, D_, D_);

    const int rope_total = B_ * S_ * H_ * (HD_ / 2);
    rope_kernel<<<(rope_total + 255) / 256, 256>>>(q, k, fc, fs);

    size_t fsm = (size_t)(4 * 64 * FP + 3 * 64 + 256) * sizeof(float);
    cudaFuncSetAttribute(flash_kernel, cudaFuncAttributeMaxDynamicSharedMemorySize, (int)fsm);
    flash_kernel<<<dim3(S_ / 64, B_ * H_), 256, fsm>>>(q, k, v, attn);

    gemm_bf16x3<<<ggrid, 256>>>(attn, wo, out, M_, D_, D_);
}

// round 5
// speedup vs baseline: 2.1361x; 1.7426x over previous
#include <cuda_runtime.h>
#include <cuda_bf16.h>
#include <stdint.h>
#include <math.h>

// Problem constants
#define B_ 2
#define S_ 2048
#define D_ 1024
#define H_ 16
#define HD_ 64
#define M_ (B_ * S_)

// Scratch (device globals; no allocations allowed)
__device__ float g_q[B_ * S_ * D_];
__device__ float g_k[B_ * S_ * D_];
__device__ float g_v[B_ * S_ * D_];
__device__ float g_attn[B_ * S_ * D_];

// ---------------------------------------------------------------------------
// Common helpers
// ---------------------------------------------------------------------------
__device__ __forceinline__ void cp_async16(unsigned int dst, const void* src) {
    asm volatile("cp.async.cg.shared.global [%0], [%1], 16;\n" :: "r"(dst), "l"(src));
}
__device__ __forceinline__ void cp_commit() {
    asm volatile("cp.async.commit_group;\n" ::: "memory");
}
template <int N>
__device__ __forceinline__ void cp_wait() {
    asm volatile("cp.async.wait_group %0;\n" :: "n"(N) : "memory");
}

// Split two fp32 into packed bf16x2 hi and lo (low 16 bits = first element).
__device__ __forceinline__ void split2(float x, float y,
                                       unsigned int& hi, unsigned int& lo) {
    __nv_bfloat16 hx = __float2bfloat16_rn(x);
    __nv_bfloat16 hy = __float2bfloat16_rn(y);
    float rx = x - __bfloat162float(hx);
    float ry = y - __bfloat162float(hy);
    __nv_bfloat16 lx = __float2bfloat16_rn(rx);
    __nv_bfloat16 ly = __float2bfloat16_rn(ry);
    unsigned short hxu = *(unsigned short*)&hx;
    unsigned short hyu = *(unsigned short*)&hy;
    unsigned short lxu = *(unsigned short*)&lx;
    unsigned short lyu = *(unsigned short*)&ly;
    hi = (unsigned int)hxu | ((unsigned int)hyu << 16);
    lo = (unsigned int)lxu | ((unsigned int)lyu << 16);
}

__device__ __forceinline__ void mma_bf16(float* c, const unsigned int* a,
                                         const unsigned int* b) {
    asm volatile(
        "mma.sync.aligned.m16n8k16.row.col.f32.bf16.bf16.f32 "
        "{%0,%1,%2,%3}, {%4,%5,%6,%7}, {%8,%9}, {%0,%1,%2,%3};\n"
        : "+f"(c[0]), "+f"(c[1]), "+f"(c[2]), "+f"(c[3])
        : "r"(a[0]), "r"(a[1]), "r"(a[2]), "r"(a[3]),
          "r"(b[0]), "r"(b[1]));
}

__device__ __forceinline__ void ldsm4(unsigned int& r0, unsigned int& r1,
                                      unsigned int& r2, unsigned int& r3,
                                      unsigned int addr) {
    asm volatile("ldmatrix.sync.aligned.m8n8.x4.shared.b16 {%0,%1,%2,%3}, [%4];"
                 : "=r"(r0), "=r"(r1), "=r"(r2), "=r"(r3) : "r"(addr));
}
__device__ __forceinline__ void ldsm4t(unsigned int& r0, unsigned int& r1,
                                       unsigned int& r2, unsigned int& r3,
                                       unsigned int addr) {
    asm volatile("ldmatrix.sync.aligned.m8n8.x4.trans.shared.b16 {%0,%1,%2,%3}, [%4];"
                 : "=r"(r0), "=r"(r1), "=r"(r2), "=r"(r3) : "r"(addr));
}

// ---------------------------------------------------------------------------
// bf16-split (3-term) tensor-core GEMM (unchanged from R4, known good)
// ---------------------------------------------------------------------------
#define BM 128
#define BN 128
#define BKT 16
#define AST 20
#define BST 132

__global__ __launch_bounds__(256) void gemm_bf16x3(const float* __restrict__ A,
                                                   const float* __restrict__ B,
                                                   float* __restrict__ C,
                                                   int M, int N, int K) {
    __shared__ float As[2][BM * AST];
    __shared__ float Bs[2][BKT * BST];

    const int tid = threadIdx.x;
    const int bm = blockIdx.y * BM;
    const int bn = blockIdx.x * BN;

    const int wid = tid >> 5;
    const int lane = tid & 31;
    const int wm = (wid >> 2) * 64;
    const int wn = (wid & 3) * 32;
    const int g = lane >> 2;
    const int t4 = lane & 3;

    const int aRow0 = tid >> 2;
    const int aC40  = tid & 3;
    const int aRow1 = aRow0 + 64;
    const int bRow0 = tid >> 5;
    const int bC40  = tid & 31;
    const int bRow1 = bRow0 + 8;

    const unsigned int sA = (unsigned int)__cvta_generic_to_shared(&As[0][0]);
    const unsigned int sB = (unsigned int)__cvta_generic_to_shared(&Bs[0][0]);
    const unsigned int stageA = BM * AST * 4;
    const unsigned int stageB = BKT * BST * 4;

    float cc[4][4][4];
#pragma unroll
    for (int i = 0; i < 4; i++)
#pragma unroll
        for (int j = 0; j < 4; j++)
#pragma unroll
            for (int r = 0; r < 4; r++) cc[i][j][r] = 0.f;

    const int Kt = K / BKT;

    auto issue_stage = [&](int kt, int buf) {
        const float* Ag0 = A + (long)(bm + aRow0) * K + kt * BKT + aC40 * 4;
        cp_async16(sA + buf * stageA + (unsigned)(aRow0 * AST + aC40 * 4) * 4, Ag0);
        const float* Ag1 = A + (long)(bm + aRow1) * K + kt * BKT + aC40 * 4;
        cp_async16(sA + buf * stageA + (unsigned)(aRow1 * AST + aC40 * 4) * 4, Ag1);
        const float* Bg0 = B + (long)(kt * BKT + bRow0) * N + bn + bC40 * 4;
        cp_async16(sB + buf * stageB + (unsigned)(bRow0 * BST + bC40 * 4) * 4, Bg0);
        const float* Bg1 = B + (long)(kt * BKT + bRow1) * N + bn + bC40 * 4;
        cp_async16(sB + buf * stageB + (unsigned)(bRow1 * BST + bC40 * 4) * 4, Bg1);
        cp_commit();
    };

    issue_stage(0, 0);

    for (int kt = 0; kt < Kt; kt++) {
        const int buf = kt & 1;
        if (kt + 1 < Kt) {
            issue_stage(kt + 1, buf ^ 1);
            cp_wait<1>();
        } else {
            cp_wait<0>();
        }
        __syncthreads();

        const float* Asb = &As[buf][0];
        const float* Bsb = &Bs[buf][0];

        unsigned int ah[4][4], al[4][4];
#pragma unroll
        for (int mt = 0; mt < 4; mt++) {
            const int r0 = wm + mt * 16;
            float2 u0 = *(const float2*)&Asb[(r0 + g) * AST + 2 * t4];
            float2 u1 = *(const float2*)&Asb[(r0 + g + 8) * AST + 2 * t4];
            float2 u2 = *(const float2*)&Asb[(r0 + g) * AST + 2 * t4 + 8];
            float2 u3 = *(const float2*)&Asb[(r0 + g + 8) * AST + 2 * t4 + 8];
            split2(u0.x, u0.y, ah[mt][0], al[mt][0]);
            split2(u1.x, u1.y, ah[mt][1], al[mt][1]);
            split2(u2.x, u2.y, ah[mt][2], al[mt][2]);
            split2(u3.x, u3.y, ah[mt][3], al[mt][3]);
        }
        unsigned int bh[4][2], bl[4][2];
#pragma unroll
        for (int nt = 0; nt < 4; nt++) {
            const int c0 = wn + nt * 8 + g;
            float x0 = Bsb[(2 * t4) * BST + c0];
            float y0 = Bsb[(2 * t4 + 1) * BST + c0];
            float x1 = Bsb[(2 * t4 + 8) * BST + c0];
            float y1 = Bsb[(2 * t4 + 9) * BST + c0];
            split2(x0, y0, bh[nt][0], bl[nt][0]);
            split2(x1, y1, bh[nt][1], bl[nt][1]);
        }

#pragma unroll
        for (int mt = 0; mt < 4; mt++) {
#pragma unroll
            for (int nt = 0; nt < 4; nt++) {
                mma_bf16(cc[mt][nt], ah[mt], bl[nt]);
                mma_bf16(cc[mt][nt], al[mt], bh[nt]);
                mma_bf16(cc[mt][nt], ah[mt], bh[nt]);
            }
        }
        __syncthreads();
    }

#pragma unroll
    for (int mt = 0; mt < 4; mt++) {
#pragma unroll
        for (int nt = 0; nt < 4; nt++) {
            const int row = bm + wm + mt * 16 + g;
            const int col = bn + wn + nt * 8 + 2 * t4;
            *(float2*)(C + (long)row * N + col) =
                make_float2(cc[mt][nt][0], cc[mt][nt][1]);
            *(float2*)(C + (long)(row + 8) * N + col) =
                make_float2(cc[mt][nt][2], cc[mt][nt][3]);
        }
    }
}

// ---------------------------------------------------------------------------
// RoPE applied in-place to q and k (unchanged)
// ---------------------------------------------------------------------------
__global__ void rope_kernel(float* __restrict__ q, float* __restrict__ k,
                            const float* __restrict__ fc,
                            const float* __restrict__ fs) {
    int t = blockIdx.x * blockDim.x + threadIdx.x;
    const int total = B_ * S_ * H_ * (HD_ / 2);
    if (t >= total) return;
    int p = t & 31;
    int h = (t >> 5) & 15;
    int bs = t >> 9;
    int s = bs & (S_ - 1);
    float c = fc[s * 32 + p];
    float sn = fs[s * 32 + p];
    long base = (long)bs * D_ + h * HD_ + 2 * p;
    float2 qv = *(float2*)(q + base);
    *(float2*)(q + base) = make_float2(qv.x * c - qv.y * sn, qv.x * sn + qv.y * c);
    float2 kv = *(float2*)(k + base);
    *(float2*)(k + base) = make_float2(kv.x * c - kv.y * sn, kv.x * sn + kv.y * c);
}

// ---------------------------------------------------------------------------
// Flash attention with bf16-split tensor-core MMAs.
// 128 threads = 4 warps; warp w owns query rows [w*16, w*16+16).
// Br = Bc = 64, HD = 64. K,V tiles in SMEM as bf16 hi/lo, row stride 72.
// Q fragments hoisted to registers. Scores/P entirely in registers.
// ---------------------------------------------------------------------------
#define KP 72   // bf16 elements per SMEM row (64 used + 8 pad)

__global__ __launch_bounds__(128) void flash_mma(const float* __restrict__ q,
                                                 const float* __restrict__ k,
                                                 const float* __restrict__ v,
                                                 float* __restrict__ o) {
    __shared__ __nv_bfloat16 Khi[64 * KP];
    __shared__ __nv_bfloat16 Klo[64 * KP];
    __shared__ __nv_bfloat16 Vhi[64 * KP];
    __shared__ __nv_bfloat16 Vlo[64 * KP];

    const int tid = threadIdx.x;
    const int lane = tid & 31;
    const int wid = tid >> 5;
    const int g = lane >> 2;        // 0..7
    const int t4 = lane & 3;        // 0..3
    const int wrow = wid * 16;      // warp's first query row in tile

    const int qt = blockIdx.x;
    const int bh = blockIdx.y;
    const int q0 = qt * 64;

    const long headoff = (long)(bh >> 4) * S_ * D_ + (bh & 15) * HD_;
    const float* qb = q + headoff;
    const float* kb = k + headoff;
    const float* vb = v + headoff;
    float* ob = o + headoff;

    // ---- Stage Q (scaled by 1/8) into Khi/Klo, extract A-fragments ----
    for (int e = tid; e < 2048; e += 128) {
        int row = e >> 5;
        int dp = (e & 31) * 2;
        float2 u = *(const float2*)(qb + (long)(q0 + row) * D_ + dp);
        u.x *= 0.125f; u.y *= 0.125f;
        unsigned int hi, lo;
        split2(u.x, u.y, hi, lo);
        *(unsigned int*)&Khi[row * KP + dp] = hi;
        *(unsigned int*)&Klo[row * KP + dp] = lo;
    }
    __syncthreads();

    unsigned int qh[4][4], ql[4][4];
#pragma unroll
    for (int kc = 0; kc < 4; kc++) {
        const int cb = kc * 16 + 2 * t4;
        qh[kc][0] = *(unsigned int*)&Khi[(wrow + g) * KP + cb];
        qh[kc][1] = *(unsigned int*)&Khi[(wrow + g + 8) * KP + cb];
        qh[kc][2] = *(unsigned int*)&Khi[(wrow + g) * KP + cb + 8];
        qh[kc][3] = *(unsigned int*)&Khi[(wrow + g + 8) * KP + cb + 8];
        ql[kc][0] = *(unsigned int*)&Klo[(wrow + g) * KP + cb];
        ql[kc][1] = *(unsigned int*)&Klo[(wrow + g + 8) * KP + cb];
        ql[kc][2] = *(unsigned int*)&Klo[(wrow + g) * KP + cb + 8];
        ql[kc][3] = *(unsigned int*)&Klo[(wrow + g + 8) * KP + cb + 8];
    }
    __syncthreads();

    float oacc[8][4];
#pragma unroll
    for (int nt = 0; nt < 8; nt++)
#pragma unroll
        for (int r = 0; r < 4; r++) oacc[nt][r] = 0.f;
    float m0 = -1e30f, m1 = -1e30f, l0 = 0.f, l1 = 0.f;

    // ldmatrix lane-address components (constant across jt)
    const int grp = lane >> 3;      // 0..3
    const int rr  = lane & 7;       // 0..7

    for (int jt = 0; jt <= qt; jt++) {
        const int k0 = jt * 64;
        // ---- Load K,V tiles, split to bf16 hi/lo ----
        for (int e = tid; e < 2048; e += 128) {
            int row = e >> 5;
            int dp = (e & 31) * 2;
            const long goff = (long)(k0 + row) * D_ + dp;
            float2 u = *(const float2*)(kb + goff);
            unsigned int hi, lo;
            split2(u.x, u.y, hi, lo);
            *(unsigned int*)&Khi[row * KP + dp] = hi;
            *(unsigned int*)&Klo[row * KP + dp] = lo;
            float2 w = *(const float2*)(vb + goff);
            split2(w.x, w.y, hi, lo);
            *(unsigned int*)&Vhi[row * KP + dp] = hi;
            *(unsigned int*)&Vlo[row * KP + dp] = lo;
        }
        __syncthreads();

        // ---- S = (Q/8) @ K^T via 3-term bf16 MMAs ----
        float sc[8][4];
#pragma unroll
        for (int nt = 0; nt < 8; nt++)
#pragma unroll
            for (int r = 0; r < 4; r++) sc[nt][r] = 0.f;

#pragma unroll
        for (int dc = 0; dc < 4; dc++) {
#pragma unroll
            for (int np = 0; np < 4; np++) {
                const int ntA = 2 * np, ntB = 2 * np + 1;
                // non-trans ldmatrix: blk0=b0(ntA) blk1=b1(ntA) blk2=b0(ntB) blk3=b1(ntB)
                const int keysel = (grp & 2) ? ntB : ntA;
                const int colsel = dc * 16 + ((grp & 1) ? 8 : 0);
                unsigned int ahh = (unsigned int)__cvta_generic_to_shared(
                    &Khi[(keysel * 8 + rr) * KP + colsel]);
                unsigned int ahl = (unsigned int)__cvta_generic_to_shared(
                    &Klo[(keysel * 8 + rr) * KP + colsel]);
                unsigned int bhA[2], bhB[2], blA[2], blB[2];
                ldsm4(bhA[0], bhA[1], bhB[0], bhB[1], ahh);
                ldsm4(blA[0], blA[1], blB[0], blB[1], ahl);
                mma_bf16(sc[ntA], qh[dc], blA);
                mma_bf16(sc[ntA], ql[dc], bhA);
                mma_bf16(sc[ntA], qh[dc], bhA);
                mma_bf16(sc[ntB], qh[dc], blB);
                mma_bf16(sc[ntB], ql[dc], bhB);
                mma_bf16(sc[ntB], qh[dc], bhB);
            }
        }

        // ---- Causal mask (diag tile only) ----
        if (jt == qt) {
            const int r0l = wrow + g;
#pragma unroll
            for (int nt = 0; nt < 8; nt++) {
                const int c = nt * 8 + 2 * t4;
                if (c > r0l)      sc[nt][0] = -1e30f;
                if (c + 1 > r0l)  sc[nt][1] = -1e30f;
                if (c > r0l + 8)      sc[nt][2] = -1e30f;
                if (c + 1 > r0l + 8)  sc[nt][3] = -1e30f;
            }
        }

        // ---- Online softmax (rows g and g+8), quad reduction ----
        float tm0 = -1e30f, tm1 = -1e30f;
#pragma unroll
        for (int nt = 0; nt < 8; nt++) {
            tm0 = fmaxf(tm0, fmaxf(sc[nt][0], sc[nt][1]));
            tm1 = fmaxf(tm1, fmaxf(sc[nt][2], sc[nt][3]));
        }
        tm0 = fmaxf(tm0, __shfl_xor_sync(0xffffffffu, tm0, 1));
        tm0 = fmaxf(tm0, __shfl_xor_sync(0xffffffffu, tm0, 2));
        tm1 = fmaxf(tm1, __shfl_xor_sync(0xffffffffu, tm1, 1));
        tm1 = fmaxf(tm1, __shfl_xor_sync(0xffffffffu, tm1, 2));

        float mn0 = fmaxf(m0, tm0);
        float mn1 = fmaxf(m1, tm1);
        float al0 = __expf(m0 - mn0);
        float al1 = __expf(m1 - mn1);
        m0 = mn0; m1 = mn1;

        float ps0 = 0.f, ps1 = 0.f;
#pragma unroll
        for (int nt = 0; nt < 8; nt++) {
            sc[nt][0] = __expf(sc[nt][0] - m0);
            sc[nt][1] = __expf(sc[nt][1] - m0);
            sc[nt][2] = __expf(sc[nt][2] - m1);
            sc[nt][3] = __expf(sc[nt][3] - m1);
            ps0 += sc[nt][0] + sc[nt][1];
            ps1 += sc[nt][2] + sc[nt][3];
        }
        ps0 += __shfl_xor_sync(0xffffffffu, ps0, 1);
        ps0 += __shfl_xor_sync(0xffffffffu, ps0, 2);
        ps1 += __shfl_xor_sync(0xffffffffu, ps1, 1);
        ps1 += __shfl_xor_sync(0xffffffffu, ps1, 2);
        l0 = l0 * al0 + ps0;
        l1 = l1 * al1 + ps1;

#pragma unroll
        for (int nt = 0; nt < 8; nt++) {
            oacc[nt][0] *= al0; oacc[nt][1] *= al0;
            oacc[nt][2] *= al1; oacc[nt][3] *= al1;
        }

        // ---- O += P @ V via 3-term bf16 MMAs (P from score regs) ----
#pragma unroll
        for (int kc = 0; kc < 4; kc++) {
            unsigned int ph[4], pl[4];
            split2(sc[2 * kc][0], sc[2 * kc][1], ph[0], pl[0]);
            split2(sc[2 * kc][2], sc[2 * kc][3], ph[1], pl[1]);
            split2(sc[2 * kc + 1][0], sc[2 * kc + 1][1], ph[2], pl[2]);
            split2(sc[2 * kc + 1][2], sc[2 * kc + 1][3], ph[3], pl[3]);
#pragma unroll
            for (int np = 0; np < 4; np++) {
                const int ntA = 2 * np, ntB = 2 * np + 1;
                // trans ldmatrix: blk0=b0(ntA) blk1=b1(ntA) blk2=b0(ntB) blk3=b1(ntB)
                const int rowsel = kc * 16 + ((grp & 1) ? 8 : 0) + rr;
                const int colsel = ((grp & 2) ? ntB : ntA) * 8;
                unsigned int avh = (unsigned int)__cvta_generic_to_shared(
                    &Vhi[rowsel * KP + colsel]);
                unsigned int avl = (unsigned int)__cvta_generic_to_shared(
                    &Vlo[rowsel * KP + colsel]);
                unsigned int vhA[2], vhB[2], vlA[2], vlB[2];
                ldsm4t(vhA[0], vhA[1], vhB[0], vhB[1], avh);
                ldsm4t(vlA[0], vlA[1], vlB[0], vlB[1], avl);
                mma_bf16(oacc[ntA], ph, vlA);
                mma_bf16(oacc[ntA], pl, vhA);
                mma_bf16(oacc[ntA], ph, vhA);
                mma_bf16(oacc[ntB], ph, vlB);
                mma_bf16(oacc[ntB], pl, vhB);
                mma_bf16(oacc[ntB], ph, vhB);
            }
        }
        __syncthreads();
    }

    // ---- Normalize and write out ----
    const float inv0 = 1.f / l0;
    const float inv1 = 1.f / l1;
    const int row0 = q0 + wrow + g;
#pragma unroll
    for (int nt = 0; nt < 8; nt++) {
        const int col = nt * 8 + 2 * t4;
        *(float2*)(ob + (long)row0 * D_ + col) =
            make_float2(oacc[nt][0] * inv0, oacc[nt][1] * inv0);
        *(float2*)(ob + (long)(row0 + 8) * D_ + col) =
            make_float2(oacc[nt][2] * inv1, oacc[nt][3] * inv1);
    }
}

// ---------------------------------------------------------------------------
// Launch
// ---------------------------------------------------------------------------
extern "C" void kernel_launch(void* const* d_in, const int* in_sizes, int n_in,
                              void* d_out, int out_size) {
    const float* x  = (const float*)d_in[0];
    const float* wq = (const float*)d_in[1];
    const float* wk = (const float*)d_in[2];
    const float* wv = (const float*)d_in[3];
    const float* wo = (const float*)d_in[4];
    const float* fc = (const float*)d_in[5];
    const float* fs = (const float*)d_in[6];
    float* out = (float*)d_out;

    float *q, *k, *v, *attn;
    cudaGetSymbolAddress((void**)&q, g_q);
    cudaGetSymbolAddress((void**)&k, g_k);
    cudaGetSymbolAddress((void**)&v, g_v);
    cudaGetSymbolAddress((void**)&attn, g_attn);

    dim3 ggrid(D_ / BN, M_ / BM);   // (8, 32)
    gemm_bf16x3<<<ggrid, 256>>>(x, wq, q, M_, D_, D_);
    gemm_bf16x3<<<ggrid, 256>>>(x, wk, k, M_, D_, D_);
    gemm_bf16x3<<<ggrid, 256>>>(x, wv, v, M_, D_, D_);

    const int rope_total = B_ * S_ * H_ * (HD_ / 2);
    rope_kernel<<<(rope_total + 255) / 256, 256>>>(q, k, fc, fs);

    flash_mma<<<dim3(S_ / 64, B_ * H_), 128>>>(q, k, v, attn);

    gemm_bf16x3<<<ggrid, 256>>>(attn, wo, out, M_, D_, D_);
}

// round 6
// speedup vs baseline: 2.3988x; 1.1230x over previous
#include <cuda_runtime.h>
#include <cuda_bf16.h>
#include <stdint.h>
#include <math.h>

// Problem constants
#define B_ 2
#define S_ 2048
#define D_ 1024
#define H_ 16
#define HD_ 64
#define M_ (B_ * S_)

// Scratch (device globals; no allocations allowed)
__device__ float g_q[B_ * S_ * D_];
__device__ float g_k[B_ * S_ * D_];
__device__ float g_v[B_ * S_ * D_];
__device__ float g_attn[B_ * S_ * D_];
__device__ __nv_bfloat16 g_qhi[B_ * S_ * D_];
__device__ __nv_bfloat16 g_qlo[B_ * S_ * D_];
__device__ __nv_bfloat16 g_khi[B_ * S_ * D_];
__device__ __nv_bfloat16 g_klo[B_ * S_ * D_];
__device__ __nv_bfloat16 g_vhi[B_ * S_ * D_];
__device__ __nv_bfloat16 g_vlo[B_ * S_ * D_];

// ---------------------------------------------------------------------------
// Common helpers
// ---------------------------------------------------------------------------
__device__ __forceinline__ void cp_async16(unsigned int dst, const void* src) {
    asm volatile("cp.async.cg.shared.global [%0], [%1], 16;\n" :: "r"(dst), "l"(src));
}
__device__ __forceinline__ void cp_commit() {
    asm volatile("cp.async.commit_group;\n" ::: "memory");
}
template <int N>
__device__ __forceinline__ void cp_wait() {
    asm volatile("cp.async.wait_group %0;\n" :: "n"(N) : "memory");
}

__device__ __forceinline__ float ex2f(float x) {
    float y;
    asm("ex2.approx.ftz.f32 %0, %1;" : "=f"(y) : "f"(x));
    return y;
}

// Split two fp32 into packed bf16x2 hi and lo (low 16 bits = first element).
__device__ __forceinline__ void split2(float x, float y,
                                       unsigned int& hi, unsigned int& lo) {
    __nv_bfloat16 hx = __float2bfloat16_rn(x);
    __nv_bfloat16 hy = __float2bfloat16_rn(y);
    float rx = x - __bfloat162float(hx);
    float ry = y - __bfloat162float(hy);
    __nv_bfloat16 lx = __float2bfloat16_rn(rx);
    __nv_bfloat16 ly = __float2bfloat16_rn(ry);
    unsigned short hxu = *(unsigned short*)&hx;
    unsigned short hyu = *(unsigned short*)&hy;
    unsigned short lxu = *(unsigned short*)&lx;
    unsigned short lyu = *(unsigned short*)&ly;
    hi = (unsigned int)hxu | ((unsigned int)hyu << 16);
    lo = (unsigned int)lxu | ((unsigned int)lyu << 16);
}

__device__ __forceinline__ void mma_bf16(float* c, const unsigned int* a,
                                         const unsigned int* b) {
    asm volatile(
        "mma.sync.aligned.m16n8k16.row.col.f32.bf16.bf16.f32 "
        "{%0,%1,%2,%3}, {%4,%5,%6,%7}, {%8,%9}, {%0,%1,%2,%3};\n"
        : "+f"(c[0]), "+f"(c[1]), "+f"(c[2]), "+f"(c[3])
        : "r"(a[0]), "r"(a[1]), "r"(a[2]), "r"(a[3]),
          "r"(b[0]), "r"(b[1]));
}

__device__ __forceinline__ void ldsm4(unsigned int& r0, unsigned int& r1,
                                      unsigned int& r2, unsigned int& r3,
                                      unsigned int addr) {
    asm volatile("ldmatrix.sync.aligned.m8n8.x4.shared.b16 {%0,%1,%2,%3}, [%4];"
                 : "=r"(r0), "=r"(r1), "=r"(r2), "=r"(r3) : "r"(addr));
}
__device__ __forceinline__ void ldsm4t(unsigned int& r0, unsigned int& r1,
                                       unsigned int& r2, unsigned int& r3,
                                       unsigned int addr) {
    asm volatile("ldmatrix.sync.aligned.m8n8.x4.trans.shared.b16 {%0,%1,%2,%3}, [%4];"
                 : "=r"(r0), "=r"(r1), "=r"(r2), "=r"(r3) : "r"(addr));
}

// ---------------------------------------------------------------------------
// bf16-split (3-term) tensor-core GEMM core (shared by qkv + output GEMMs)
// 128x128x16 block tile, 8 warps (2x4), 64x32 warp tile, m16n8k16 bf16 mma.
// ---------------------------------------------------------------------------
#define BM 128
#define BN 128
#define BKT 16
#define AST 20
#define BST 132

__device__ __forceinline__ void gemm_core(const float* __restrict__ A,
                                          const float* __restrict__ B,
                                          float* __restrict__ C,
                                          int M, int N, int K,
                                          int bm, int bn) {
    __shared__ float As[2][BM * AST];
    __shared__ float Bs[2][BKT * BST];

    const int tid = threadIdx.x;
    const int wid = tid >> 5;
    const int lane = tid & 31;
    const int wm = (wid >> 2) * 64;
    const int wn = (wid & 3) * 32;
    const int g = lane >> 2;
    const int t4 = lane & 3;

    const int aRow0 = tid >> 2;
    const int aC40  = tid & 3;
    const int aRow1 = aRow0 + 64;
    const int bRow0 = tid >> 5;
    const int bC40  = tid & 31;
    const int bRow1 = bRow0 + 8;

    const unsigned int sA = (unsigned int)__cvta_generic_to_shared(&As[0][0]);
    const unsigned int sB = (unsigned int)__cvta_generic_to_shared(&Bs[0][0]);
    const unsigned int stageA = BM * AST * 4;
    const unsigned int stageB = BKT * BST * 4;

    float cc[4][4][4];
#pragma unroll
    for (int i = 0; i < 4; i++)
#pragma unroll
        for (int j = 0; j < 4; j++)
#pragma unroll
            for (int r = 0; r < 4; r++) cc[i][j][r] = 0.f;

    const int Kt = K / BKT;

    auto issue_stage = [&](int kt, int buf) {
        const float* Ag0 = A + (long)(bm + aRow0) * K + kt * BKT + aC40 * 4;
        cp_async16(sA + buf * stageA + (unsigned)(aRow0 * AST + aC40 * 4) * 4, Ag0);
        const float* Ag1 = A + (long)(bm + aRow1) * K + kt * BKT + aC40 * 4;
        cp_async16(sA + buf * stageA + (unsigned)(aRow1 * AST + aC40 * 4) * 4, Ag1);
        const float* Bg0 = B + (long)(kt * BKT + bRow0) * N + bn + bC40 * 4;
        cp_async16(sB + buf * stageB + (unsigned)(bRow0 * BST + bC40 * 4) * 4, Bg0);
        const float* Bg1 = B + (long)(kt * BKT + bRow1) * N + bn + bC40 * 4;
        cp_async16(sB + buf * stageB + (unsigned)(bRow1 * BST + bC40 * 4) * 4, Bg1);
        cp_commit();
    };

    issue_stage(0, 0);

    for (int kt = 0; kt < Kt; kt++) {
        const int buf = kt & 1;
        if (kt + 1 < Kt) {
            issue_stage(kt + 1, buf ^ 1);
            cp_wait<1>();
        } else {
            cp_wait<0>();
        }
        __syncthreads();

        const float* Asb = &As[buf][0];
        const float* Bsb = &Bs[buf][0];

        unsigned int ah[4][4], al[4][4];
#pragma unroll
        for (int mt = 0; mt < 4; mt++) {
            const int r0 = wm + mt * 16;
            float2 u0 = *(const float2*)&Asb[(r0 + g) * AST + 2 * t4];
            float2 u1 = *(const float2*)&Asb[(r0 + g + 8) * AST + 2 * t4];
            float2 u2 = *(const float2*)&Asb[(r0 + g) * AST + 2 * t4 + 8];
            float2 u3 = *(const float2*)&Asb[(r0 + g + 8) * AST + 2 * t4 + 8];
            split2(u0.x, u0.y, ah[mt][0], al[mt][0]);
            split2(u1.x, u1.y, ah[mt][1], al[mt][1]);
            split2(u2.x, u2.y, ah[mt][2], al[mt][2]);
            split2(u3.x, u3.y, ah[mt][3], al[mt][3]);
        }
        unsigned int bh[4][2], bl[4][2];
#pragma unroll
        for (int nt = 0; nt < 4; nt++) {
            const int c0 = wn + nt * 8 + g;
            float x0 = Bsb[(2 * t4) * BST + c0];
            float y0 = Bsb[(2 * t4 + 1) * BST + c0];
            float x1 = Bsb[(2 * t4 + 8) * BST + c0];
            float y1 = Bsb[(2 * t4 + 9) * BST + c0];
            split2(x0, y0, bh[nt][0], bl[nt][0]);
            split2(x1, y1, bh[nt][1], bl[nt][1]);
        }

#pragma unroll
        for (int mt = 0; mt < 4; mt++) {
#pragma unroll
            for (int nt = 0; nt < 4; nt++) {
                mma_bf16(cc[mt][nt], ah[mt], bl[nt]);
                mma_bf16(cc[mt][nt], al[mt], bh[nt]);
                mma_bf16(cc[mt][nt], ah[mt], bh[nt]);
            }
        }
        __syncthreads();
    }

#pragma unroll
    for (int mt = 0; mt < 4; mt++) {
#pragma unroll
        for (int nt = 0; nt < 4; nt++) {
            const int row = bm + wm + mt * 16 + g;
            const int col = bn + wn + nt * 8 + 2 * t4;
            *(float2*)(C + (long)row * N + col) =
                make_float2(cc[mt][nt][0], cc[mt][nt][1]);
            *(float2*)(C + (long)(row + 8) * N + col) =
                make_float2(cc[mt][nt][2], cc[mt][nt][3]);
        }
    }
}

// Merged QKV projection: blockIdx.x in [0,24): sel = x>>3 picks wq/wk/wv.
__global__ __launch_bounds__(256) void qkv_gemm(const float* __restrict__ x,
                                                const float* __restrict__ wq,
                                                const float* __restrict__ wk,
                                                const float* __restrict__ wv,
                                                float* __restrict__ q,
                                                float* __restrict__ k,
                                                float* __restrict__ v) {
    const int sel = blockIdx.x >> 3;
    const int bn = (blockIdx.x & 7) * BN;
    const int bm = blockIdx.y * BM;
    const float* W = (sel == 0) ? wq : (sel == 1) ? wk : wv;
    float* C = (sel == 0) ? q : (sel == 1) ? k : v;
    gemm_core(x, W, C, M_, D_, D_, bm, bn);
}

__global__ __launch_bounds__(256) void out_gemm(const float* __restrict__ A,
                                                const float* __restrict__ W,
                                                float* __restrict__ C) {
    gemm_core(A, W, C, M_, D_, D_, blockIdx.y * BM, blockIdx.x * BN);
}

// ---------------------------------------------------------------------------
// Fused RoPE + bf16 hi/lo split. Q pre-scaled by 0.125*log2(e) so QK scores
// come out in log2 domain (softmax then uses ex2 directly).
// Each thread handles one (row, pair) for q,k (rope) and v (plain split).
// ---------------------------------------------------------------------------
#define QSCALE 0.1803368801111204f   // 0.125 * log2(e)

__global__ void convert_kernel(const float* __restrict__ q,
                               const float* __restrict__ k,
                               const float* __restrict__ v,
                               const float* __restrict__ fc,
                               const float* __restrict__ fs,
                               __nv_bfloat16* __restrict__ qhi,
                               __nv_bfloat16* __restrict__ qlo,
                               __nv_bfloat16* __restrict__ khi,
                               __nv_bfloat16* __restrict__ klo,
                               __nv_bfloat16* __restrict__ vhi,
                               __nv_bfloat16* __restrict__ vlo) {
    int t = blockIdx.x * blockDim.x + threadIdx.x;
    const int total = B_ * S_ * D_ / 2;
    if (t >= total) return;
    int row = t >> 9;            // b*S + s
    int cp = t & 511;            // pair index within row
    int p = cp & 31;             // rope pair 0..31
    int s = row & (S_ - 1);
    float c = fc[s * 32 + p];
    float sn = fs[s * 32 + p];
    long base = (long)row * D_ + cp * 2;

    float2 qv = *(const float2*)(q + base);
    float qx = (qv.x * c - qv.y * sn) * QSCALE;
    float qy = (qv.x * sn + qv.y * c) * QSCALE;
    unsigned int hi, lo;
    split2(qx, qy, hi, lo);
    *(unsigned int*)(qhi + base) = hi;
    *(unsigned int*)(qlo + base) = lo;

    float2 kv = *(const float2*)(k + base);
    float kx = kv.x * c - kv.y * sn;
    float ky = kv.x * sn + kv.y * c;
    split2(kx, ky, hi, lo);
    *(unsigned int*)(khi + base) = hi;
    *(unsigned int*)(klo + base) = lo;

    float2 vv = *(const float2*)(v + base);
    split2(vv.x, vv.y, hi, lo);
    *(unsigned int*)(vhi + base) = hi;
    *(unsigned int*)(vlo + base) = lo;
}

// ---------------------------------------------------------------------------
// Flash attention v2: pre-split bf16 inputs, cp.async double-buffered K/V.
// 128 threads = 4 warps; warp w owns query rows [w*16, w*16+16).
// Br = Bc = 64, HD = 64. Scores in log2 domain (Q pre-scaled).
// ---------------------------------------------------------------------------
#define KP 72            // bf16 elements per SMEM row (64 used + 8 pad)
#define TILE_E (64 * KP) // elements per array per stage
#define FLASH_SMEM (8 * TILE_E * 2)   // 2 stages x 4 arrays x 9216 B = 73728

__global__ __launch_bounds__(128) void flash2(const __nv_bfloat16* __restrict__ qhi,
                                              const __nv_bfloat16* __restrict__ qlo,
                                              const __nv_bfloat16* __restrict__ khi,
                                              const __nv_bfloat16* __restrict__ klo,
                                              const __nv_bfloat16* __restrict__ vhi,
                                              const __nv_bfloat16* __restrict__ vlo,
                                              float* __restrict__ o) {
    extern __shared__ __nv_bfloat16 smB[];

    const int tid = threadIdx.x;
    const int lane = tid & 31;
    const int wid = tid >> 5;
    const int g = lane >> 2;
    const int t4 = lane & 3;
    const int wrow = wid * 16;
    const int grp = lane >> 3;
    const int rr  = lane & 7;

    const int qt = blockIdx.x;
    const int bh = blockIdx.y;
    const int q0 = qt * 64;

    const long headoff = (long)(bh >> 4) * S_ * D_ + (bh & 15) * HD_;
    const __nv_bfloat16* srcp[4] = {khi + headoff, klo + headoff,
                                    vhi + headoff, vlo + headoff};
    float* ob = o + headoff;

    const unsigned int smbase = (unsigned int)__cvta_generic_to_shared(smB);

    // ---- Q fragments straight from pre-split global (once per block) ----
    unsigned int qh[4][4], ql[4][4];
    {
        const __nv_bfloat16* qhb = qhi + headoff;
        const __nv_bfloat16* qlb = qlo + headoff;
        const long r0 = (long)(q0 + wrow + g) * D_;
        const long r1 = (long)(q0 + wrow + g + 8) * D_;
#pragma unroll
        for (int kc = 0; kc < 4; kc++) {
            const int cb = kc * 16 + 2 * t4;
            qh[kc][0] = *(const unsigned int*)(qhb + r0 + cb);
            qh[kc][1] = *(const unsigned int*)(qhb + r1 + cb);
            qh[kc][2] = *(const unsigned int*)(qhb + r0 + cb + 8);
            qh[kc][3] = *(const unsigned int*)(qhb + r1 + cb + 8);
            ql[kc][0] = *(const unsigned int*)(qlb + r0 + cb);
            ql[kc][1] = *(const unsigned int*)(qlb + r1 + cb);
            ql[kc][2] = *(const unsigned int*)(qlb + r0 + cb + 8);
            ql[kc][3] = *(const unsigned int*)(qlb + r1 + cb + 8);
        }
    }

    auto issue = [&](int jt, int buf) {
        const int k0 = jt * 64;
#pragma unroll
        for (int i = 0; i < 16; i++) {
            const int G = tid + i * 128;
            const int arr = G >> 9;
            const int rem = G & 511;
            const int row = rem >> 3;
            const int ch = rem & 7;
            unsigned int dst = smbase +
                ((unsigned)((buf * 4 + arr) * TILE_E + row * KP + ch * 8)) * 2;
            cp_async16(dst, srcp[arr] + ((long)(k0 + row) * D_ + ch * 8));
        }
        cp_commit();
    };

    float oacc[8][4];
#pragma unroll
    for (int nt = 0; nt < 8; nt++)
#pragma unroll
        for (int r = 0; r < 4; r++) oacc[nt][r] = 0.f;
    float m0 = -1e30f, m1 = -1e30f, l0 = 0.f, l1 = 0.f;

    const int ntiles = qt + 1;
    issue(0, 0);

    for (int jt = 0; jt < ntiles; jt++) {
        const int buf = jt & 1;
        if (jt + 1 < ntiles) {
            issue(jt + 1, buf ^ 1);
            cp_wait<1>();
        } else {
            cp_wait<0>();
        }
        __syncthreads();

        const __nv_bfloat16* kh_s = smB + (buf * 4 + 0) * TILE_E;
        const __nv_bfloat16* kl_s = smB + (buf * 4 + 1) * TILE_E;
        const __nv_bfloat16* vh_s = smB + (buf * 4 + 2) * TILE_E;
        const __nv_bfloat16* vl_s = smB + (buf * 4 + 3) * TILE_E;

        // ---- S(log2) = Qs @ K^T via 3-term bf16 MMAs ----
        float sc[8][4];
#pragma unroll
        for (int nt = 0; nt < 8; nt++)
#pragma unroll
            for (int r = 0; r < 4; r++) sc[nt][r] = 0.f;

#pragma unroll
        for (int dc = 0; dc < 4; dc++) {
#pragma unroll
            for (int np = 0; np < 4; np++) {
                const int ntA = 2 * np, ntB = 2 * np + 1;
                const int keysel = (grp & 2) ? ntB : ntA;
                const int colsel = dc * 16 + ((grp & 1) ? 8 : 0);
                unsigned int ahh = (unsigned int)__cvta_generic_to_shared(
                    kh_s + (keysel * 8 + rr) * KP + colsel);
                unsigned int ahl = (unsigned int)__cvta_generic_to_shared(
                    kl_s + (keysel * 8 + rr) * KP + colsel);
                unsigned int bhA[2], bhB[2], blA[2], blB[2];
                ldsm4(bhA[0], bhA[1], bhB[0], bhB[1], ahh);
                ldsm4(blA[0], blA[1], blB[0], blB[1], ahl);
                mma_bf16(sc[ntA], qh[dc], blA);
                mma_bf16(sc[ntA], ql[dc], bhA);
                mma_bf16(sc[ntA], qh[dc], bhA);
                mma_bf16(sc[ntB], qh[dc], blB);
                mma_bf16(sc[ntB], ql[dc], bhB);
                mma_bf16(sc[ntB], qh[dc], bhB);
            }
        }

        // ---- Causal mask (diag tile only) ----
        if (jt == qt) {
            const int r0l = wrow + g;
#pragma unroll
            for (int nt = 0; nt < 8; nt++) {
                const int c = nt * 8 + 2 * t4;
                if (c > r0l)          sc[nt][0] = -1e30f;
                if (c + 1 > r0l)      sc[nt][1] = -1e30f;
                if (c > r0l + 8)      sc[nt][2] = -1e30f;
                if (c + 1 > r0l + 8)  sc[nt][3] = -1e30f;
            }
        }

        // ---- Online softmax (log2 domain), quad reduction ----
        float tm0 = -1e30f, tm1 = -1e30f;
#pragma unroll
        for (int nt = 0; nt < 8; nt++) {
            tm0 = fmaxf(tm0, fmaxf(sc[nt][0], sc[nt][1]));
            tm1 = fmaxf(tm1, fmaxf(sc[nt][2], sc[nt][3]));
        }
        tm0 = fmaxf(tm0, __shfl_xor_sync(0xffffffffu, tm0, 1));
        tm0 = fmaxf(tm0, __shfl_xor_sync(0xffffffffu, tm0, 2));
        tm1 = fmaxf(tm1, __shfl_xor_sync(0xffffffffu, tm1, 1));
        tm1 = fmaxf(tm1, __shfl_xor_sync(0xffffffffu, tm1, 2));

        float mn0 = fmaxf(m0, tm0);
        float mn1 = fmaxf(m1, tm1);
        float al0 = ex2f(m0 - mn0);
        float al1 = ex2f(m1 - mn1);
        m0 = mn0; m1 = mn1;

        float ps0 = 0.f, ps1 = 0.f;
#pragma unroll
        for (int nt = 0; nt < 8; nt++) {
            sc[nt][0] = ex2f(sc[nt][0] - m0);
            sc[nt][1] = ex2f(sc[nt][1] - m0);
            sc[nt][2] = ex2f(sc[nt][2] - m1);
            sc[nt][3] = ex2f(sc[nt][3] - m1);
            ps0 += sc[nt][0] + sc[nt][1];
            ps1 += sc[nt][2] + sc[nt][3];
        }
        ps0 += __shfl_xor_sync(0xffffffffu, ps0, 1);
        ps0 += __shfl_xor_sync(0xffffffffu, ps0, 2);
        ps1 += __shfl_xor_sync(0xffffffffu, ps1, 1);
        ps1 += __shfl_xor_sync(0xffffffffu, ps1, 2);
        l0 = l0 * al0 + ps0;
        l1 = l1 * al1 + ps1;

#pragma unroll
        for (int nt = 0; nt < 8; nt++) {
            oacc[nt][0] *= al0; oacc[nt][1] *= al0;
            oacc[nt][2] *= al1; oacc[nt][3] *= al1;
        }

        // ---- O += P @ V via 3-term bf16 MMAs ----
#pragma unroll
        for (int kc = 0; kc < 4; kc++) {
            unsigned int ph[4], pl[4];
            split2(sc[2 * kc][0], sc[2 * kc][1], ph[0], pl[0]);
            split2(sc[2 * kc][2], sc[2 * kc][3], ph[1], pl[1]);
            split2(sc[2 * kc + 1][0], sc[2 * kc + 1][1], ph[2], pl[2]);
            split2(sc[2 * kc + 1][2], sc[2 * kc + 1][3], ph[3], pl[3]);
#pragma unroll
            for (int np = 0; np < 4; np++) {
                const int ntA = 2 * np, ntB = 2 * np + 1;
                const int rowsel = kc * 16 + ((grp & 1) ? 8 : 0) + rr;
                const int colsel = ((grp & 2) ? ntB : ntA) * 8;
                unsigned int avh = (unsigned int)__cvta_generic_to_shared(
                    vh_s + rowsel * KP + colsel);
                unsigned int avl = (unsigned int)__cvta_generic_to_shared(
                    vl_s + rowsel * KP + colsel);
                unsigned int vhA[2], vhB[2], vlA[2], vlB[2];
                ldsm4t(vhA[0], vhA[1], vhB[0], vhB[1], avh);
                ldsm4t(vlA[0], vlA[1], vlB[0], vlB[1], avl);
                mma_bf16(oacc[ntA], ph, vlA);
                mma_bf16(oacc[ntA], pl, vhA);
                mma_bf16(oacc[ntA], ph, vhA);
                mma_bf16(oacc[ntB], ph, vlB);
                mma_bf16(oacc[ntB], pl, vhB);
                mma_bf16(oacc[ntB], ph, vhB);
            }
        }
        __syncthreads();   // all reads of buf done before it is re-filled
    }

    // ---- Normalize and write out ----
    const float inv0 = 1.f / l0;
    const float inv1 = 1.f / l1;
    const int row0 = q0 + wrow + g;
#pragma unroll
    for (int nt = 0; nt < 8; nt++) {
        const int col = nt * 8 + 2 * t4;
        *(float2*)(ob + (long)row0 * D_ + col) =
            make_float2(oacc[nt][0] * inv0, oacc[nt][1] * inv0);
        *(float2*)(ob + (long)(row0 + 8) * D_ + col) =
            make_float2(oacc[nt][2] * inv1, oacc[nt][3] * inv1);
    }
}

// ---------------------------------------------------------------------------
// Launch
// ---------------------------------------------------------------------------
extern "C" void kernel_launch(void* const* d_in, const int* in_sizes, int n_in,
                              void* d_out, int out_size) {
    const float* x  = (const float*)d_in[0];
    const float* wq = (const float*)d_in[1];
    const float* wk = (const float*)d_in[2];
    const float* wv = (const float*)d_in[3];
    const float* wo = (const float*)d_in[4];
    const float* fc = (const float*)d_in[5];
    const float* fs = (const float*)d_in[6];
    float* out = (float*)d_out;

    float *q, *k, *v, *attn;
    cudaGetSymbolAddress((void**)&q, g_q);
    cudaGetSymbolAddress((void**)&k, g_k);
    cudaGetSymbolAddress((void**)&v, g_v);
    cudaGetSymbolAddress((void**)&attn, g_attn);
    __nv_bfloat16 *qhi, *qlo, *khi, *klo, *vhi, *vlo;
    cudaGetSymbolAddress((void**)&qhi, g_qhi);
    cudaGetSymbolAddress((void**)&qlo, g_qlo);
    cudaGetSymbolAddress((void**)&khi, g_khi);
    cudaGetSymbolAddress((void**)&klo, g_klo);
    cudaGetSymbolAddress((void**)&vhi, g_vhi);
    cudaGetSymbolAddress((void**)&vlo, g_vlo);

    qkv_gemm<<<dim3(24, M_ / BM), 256>>>(x, wq, wk, wv, q, k, v);

    const int conv_total = B_ * S_ * D_ / 2;
    convert_kernel<<<(conv_total + 255) / 256, 256>>>(q, k, v, fc, fs,
                                                      qhi, qlo, khi, klo, vhi, vlo);

    cudaFuncSetAttribute(flash2, cudaFuncAttributeMaxDynamicSharedMemorySize,
                         FLASH_SMEM);
    flash2<<<dim3(S_ / 64, B_ * H_), 128, FLASH_SMEM>>>(qhi, qlo, khi, klo,
                                                        vhi, vlo, attn);

    out_gemm<<<dim3(D_ / BN, M_ / BM), 256>>>(attn, wo, out);
}

// round 7
// speedup vs baseline: 3.3369x; 1.3911x over previous
#include <cuda_runtime.h>
#include <cuda_bf16.h>
#include <stdint.h>
#include <math.h>

// Problem constants
#define B_ 2
#define S_ 2048
#define D_ 1024
#define H_ 16
#define HD_ 64
#define M_ (B_ * S_)

// Scratch (device globals; no allocations allowed)
__device__ float g_q[B_ * S_ * D_];
__device__ float g_k[B_ * S_ * D_];
__device__ float g_v[B_ * S_ * D_];
__device__ __nv_bfloat16 g_xhi[M_ * D_];
__device__ __nv_bfloat16 g_xlo[M_ * D_];
__device__ __nv_bfloat16 g_whi[4 * D_ * D_];
__device__ __nv_bfloat16 g_wlo[4 * D_ * D_];
__device__ __nv_bfloat16 g_qhi[M_ * D_];
__device__ __nv_bfloat16 g_qlo[M_ * D_];
__device__ __nv_bfloat16 g_khi[M_ * D_];
__device__ __nv_bfloat16 g_klo[M_ * D_];
__device__ __nv_bfloat16 g_vhi[M_ * D_];
__device__ __nv_bfloat16 g_vlo[M_ * D_];
__device__ __nv_bfloat16 g_ahi[M_ * D_];
__device__ __nv_bfloat16 g_alo[M_ * D_];

// ---------------------------------------------------------------------------
// Common helpers
// ---------------------------------------------------------------------------
__device__ __forceinline__ void cp_async16(unsigned int dst, const void* src) {
    asm volatile("cp.async.cg.shared.global [%0], [%1], 16;\n" :: "r"(dst), "l"(src));
}
__device__ __forceinline__ void cp_commit() {
    asm volatile("cp.async.commit_group;\n" ::: "memory");
}
template <int N>
__device__ __forceinline__ void cp_wait() {
    asm volatile("cp.async.wait_group %0;\n" :: "n"(N) : "memory");
}

__device__ __forceinline__ float ex2f(float x) {
    float y;
    asm("ex2.approx.ftz.f32 %0, %1;" : "=f"(y) : "f"(x));
    return y;
}

// Split two fp32 into packed bf16x2 hi and lo (low 16 bits = first element).
__device__ __forceinline__ void split2(float x, float y,
                                       unsigned int& hi, unsigned int& lo) {
    __nv_bfloat16 hx = __float2bfloat16_rn(x);
    __nv_bfloat16 hy = __float2bfloat16_rn(y);
    float rx = x - __bfloat162float(hx);
    float ry = y - __bfloat162float(hy);
    __nv_bfloat16 lx = __float2bfloat16_rn(rx);
    __nv_bfloat16 ly = __float2bfloat16_rn(ry);
    unsigned short hxu = *(unsigned short*)&hx;
    unsigned short hyu = *(unsigned short*)&hy;
    unsigned short lxu = *(unsigned short*)&lx;
    unsigned short lyu = *(unsigned short*)&ly;
    hi = (unsigned int)hxu | ((unsigned int)hyu << 16);
    lo = (unsigned int)lxu | ((unsigned int)lyu << 16);
}

__device__ __forceinline__ void mma_bf16(float* c, const unsigned int* a,
                                         const unsigned int* b) {
    asm volatile(
        "mma.sync.aligned.m16n8k16.row.col.f32.bf16.bf16.f32 "
        "{%0,%1,%2,%3}, {%4,%5,%6,%7}, {%8,%9}, {%0,%1,%2,%3};\n"
        : "+f"(c[0]), "+f"(c[1]), "+f"(c[2]), "+f"(c[3])
        : "r"(a[0]), "r"(a[1]), "r"(a[2]), "r"(a[3]),
          "r"(b[0]), "r"(b[1]));
}

__device__ __forceinline__ void ldsm4(unsigned int& r0, unsigned int& r1,
                                      unsigned int& r2, unsigned int& r3,
                                      unsigned int addr) {
    asm volatile("ldmatrix.sync.aligned.m8n8.x4.shared.b16 {%0,%1,%2,%3}, [%4];"
                 : "=r"(r0), "=r"(r1), "=r"(r2), "=r"(r3) : "r"(addr));
}
__device__ __forceinline__ void ldsm4t(unsigned int& r0, unsigned int& r1,
                                       unsigned int& r2, unsigned int& r3,
                                       unsigned int addr) {
    asm volatile("ldmatrix.sync.aligned.m8n8.x4.trans.shared.b16 {%0,%1,%2,%3}, [%4];"
                 : "=r"(r0), "=r"(r1), "=r"(r2), "=r"(r3) : "r"(addr));
}

// ---------------------------------------------------------------------------
// Generic fp32 -> bf16 hi/lo split kernel (processes pairs).
// ---------------------------------------------------------------------------
__global__ void split_kernel(const float* __restrict__ src,
                             __nv_bfloat16* __restrict__ dhi,
                             __nv_bfloat16* __restrict__ dlo,
                             int npairs) {
    int t = blockIdx.x * blockDim.x + threadIdx.x;
    if (t >= npairs) return;
    float2 u = *(const float2*)(src + (long)t * 2);
    unsigned int hi, lo;
    split2(u.x, u.y, hi, lo);
    *(unsigned int*)(dhi + (long)t * 2) = hi;
    *(unsigned int*)(dlo + (long)t * 2) = lo;
}

// ---------------------------------------------------------------------------
// bf16 pre-split 3-term GEMM: C[M,N] = A @ B.
// A: [M,K] bf16 hi/lo row-major. B: [K,N] bf16 hi/lo row-major. C: fp32.
// 128x128x32 tile, 8 warps (2x4), 64x32 warp tile, cp.async double-buffer.
// ---------------------------------------------------------------------------
#define BM 128
#define BN 128
#define GK 32          // K per stage (bf16)
#define ASTR 40        // A tile row stride (elems): 32 + 8 pad
#define BSTR 136       // B tile row stride (elems): 128 + 8 pad
#define A_ELE (BM * ASTR)          // 5120
#define B_ELE (GK * BSTR)          // 4352
#define STG_ELE (2 * A_ELE + 2 * B_ELE)   // 18944 elems per stage
#define GEMM_SMEM (STG_ELE * 2 * 2)       // bytes: 75776

__device__ __forceinline__ void gemm_core_bf16(
    const __nv_bfloat16* __restrict__ Ahi, const __nv_bfloat16* __restrict__ Alo,
    const __nv_bfloat16* __restrict__ Bhi, const __nv_bfloat16* __restrict__ Blo,
    float* __restrict__ C, int M, int N, int K, int bm, int bn) {
    extern __shared__ __nv_bfloat16 smG[];

    const int tid = threadIdx.x;
    const int wid = tid >> 5;
    const int lane = tid & 31;
    const int wm = (wid >> 2) * 64;
    const int wn = (wid & 3) * 32;
    const int g = lane >> 2;
    const int t4 = lane & 3;
    const int grp = lane >> 3;
    const int rr = lane & 7;

    const unsigned int smbase = (unsigned int)__cvta_generic_to_shared(smG);
    // stage layout: [Ahi | Alo | Bhi | Blo]
    const unsigned int offAhi = 0;
    const unsigned int offAlo = A_ELE;
    const unsigned int offBhi = 2 * A_ELE;
    const unsigned int offBlo = 2 * A_ELE + B_ELE;

    float cc[4][4][4];
#pragma unroll
    for (int i = 0; i < 4; i++)
#pragma unroll
        for (int j = 0; j < 4; j++)
#pragma unroll
            for (int r = 0; r < 4; r++) cc[i][j][r] = 0.f;

    const int Kt = K / GK;

    auto issue_stage = [&](int kt, int buf) {
        const unsigned int sb = smbase + (unsigned)buf * STG_ELE * 2;
        // A: 512 chunks per array; thread handles chunks tid, tid+256
#pragma unroll
        for (int i = 0; i < 2; i++) {
            const int ch = tid + i * 256;
            const int row = ch >> 2;
            const int c = ch & 3;
            const long goff = (long)(bm + row) * K + kt * GK + c * 8;
            cp_async16(sb + (offAhi + (unsigned)(row * ASTR + c * 8)) * 2, Ahi + goff);
            cp_async16(sb + (offAlo + (unsigned)(row * ASTR + c * 8)) * 2, Alo + goff);
        }
        // B: 512 chunks per array (32 rows x 16 chunks)
#pragma unroll
        for (int i = 0; i < 2; i++) {
            const int ch = tid + i * 256;
            const int row = ch >> 4;
            const int c = ch & 15;
            const long goff = (long)(kt * GK + row) * N + bn + c * 8;
            cp_async16(sb + (offBhi + (unsigned)(row * BSTR + c * 8)) * 2, Bhi + goff);
            cp_async16(sb + (offBlo + (unsigned)(row * BSTR + c * 8)) * 2, Blo + goff);
        }
        cp_commit();
    };

    issue_stage(0, 0);

    for (int kt = 0; kt < Kt; kt++) {
        const int buf = kt & 1;
        if (kt + 1 < Kt) {
            issue_stage(kt + 1, buf ^ 1);
            cp_wait<1>();
        } else {
            cp_wait<0>();
        }
        __syncthreads();

        const __nv_bfloat16* sAhi = smG + buf * STG_ELE + offAhi;
        const __nv_bfloat16* sAlo = smG + buf * STG_ELE + offAlo;
        const __nv_bfloat16* sBhi = smG + buf * STG_ELE + offBhi;
        const __nv_bfloat16* sBlo = smG + buf * STG_ELE + offBlo;

#pragma unroll
        for (int ks = 0; ks < 2; ks++) {
            // A fragments: 4 m-tiles, ldmatrix x4 (non-trans).
            // lanes 0-7: rows 0-7 col 0 | 8-15: rows 8-15 col 0
            // | 16-23: rows 0-7 col 8 | 24-31: rows 8-15 col 8
            const int arow_in = (grp & 1) * 8 + rr;
            const int acol = ks * 16 + (grp >> 1) * 8;
            unsigned int ah[4][4], al[4][4];
#pragma unroll
            for (int mt = 0; mt < 4; mt++) {
                const int r0 = wm + mt * 16 + arow_in;
                unsigned int addr_h = (unsigned int)__cvta_generic_to_shared(
                    sAhi + r0 * ASTR + acol);
                ldsm4(ah[mt][0], ah[mt][1], ah[mt][2], ah[mt][3], addr_h);
                unsigned int addr_l = (unsigned int)__cvta_generic_to_shared(
                    sAlo + r0 * ASTR + acol);
                ldsm4(al[mt][0], al[mt][1], al[mt][2], al[mt][3], addr_l);
            }
            // B fragments + MMAs: 2 n16 pairs cover the 32-wide warp tile.
            const int brow = ks * 16 + (grp & 1) * 8 + rr;
#pragma unroll
            for (int np = 0; np < 2; np++) {
                const int ntA = 2 * np, ntB = 2 * np + 1;
                const int colsel = wn + ((grp & 2) ? ntB : ntA) * 8;
                unsigned int bhA[2], bhB[2], blA[2], blB[2];
                unsigned int addr_h = (unsigned int)__cvta_generic_to_shared(
                    sBhi + brow * BSTR + colsel);
                ldsm4t(bhA[0], bhA[1], bhB[0], bhB[1], addr_h);
                unsigned int addr_l = (unsigned int)__cvta_generic_to_shared(
                    sBlo + brow * BSTR + colsel);
                ldsm4t(blA[0], blA[1], blB[0], blB[1], addr_l);
#pragma unroll
                for (int mt = 0; mt < 4; mt++) {
                    mma_bf16(cc[mt][ntA], ah[mt], blA);
                    mma_bf16(cc[mt][ntA], al[mt], bhA);
                    mma_bf16(cc[mt][ntA], ah[mt], bhA);
                    mma_bf16(cc[mt][ntB], ah[mt], blB);
                    mma_bf16(cc[mt][ntB], al[mt], bhB);
                    mma_bf16(cc[mt][ntB], ah[mt], bhB);
                }
            }
        }
        __syncthreads();
    }

    // Epilogue
#pragma unroll
    for (int mt = 0; mt < 4; mt++) {
#pragma unroll
        for (int nt = 0; nt < 4; nt++) {
            const int row = bm + wm + mt * 16 + g;
            const int col = bn + wn + nt * 8 + 2 * t4;
            *(float2*)(C + (long)row * N + col) =
                make_float2(cc[mt][nt][0], cc[mt][nt][1]);
            *(float2*)(C + (long)(row + 8) * N + col) =
                make_float2(cc[mt][nt][2], cc[mt][nt][3]);
        }
    }
}

// Merged QKV projection: blockIdx.x in [0,24): sel = x>>3 picks weight/output.
__global__ __launch_bounds__(256) void qkv_gemm(const __nv_bfloat16* __restrict__ xhi,
                                                const __nv_bfloat16* __restrict__ xlo,
                                                const __nv_bfloat16* __restrict__ whi,
                                                const __nv_bfloat16* __restrict__ wlo,
                                                float* __restrict__ q,
                                                float* __restrict__ k,
                                                float* __restrict__ v) {
    const int sel = blockIdx.x >> 3;
    const int bn = (blockIdx.x & 7) * BN;
    const int bm = blockIdx.y * BM;
    const __nv_bfloat16* Whi = whi + (long)sel * D_ * D_;
    const __nv_bfloat16* Wlo = wlo + (long)sel * D_ * D_;
    float* C = (sel == 0) ? q : (sel == 1) ? k : v;
    gemm_core_bf16(xhi, xlo, Whi, Wlo, C, M_, D_, D_, bm, bn);
}

__global__ __launch_bounds__(256) void out_gemm(const __nv_bfloat16* __restrict__ ahi,
                                                const __nv_bfloat16* __restrict__ alo,
                                                const __nv_bfloat16* __restrict__ whi,
                                                const __nv_bfloat16* __restrict__ wlo,
                                                float* __restrict__ C) {
    gemm_core_bf16(ahi, alo, whi + 3L * D_ * D_, wlo + 3L * D_ * D_, C,
                   M_, D_, D_, blockIdx.y * BM, blockIdx.x * BN);
}

// ---------------------------------------------------------------------------
// Fused RoPE + bf16 hi/lo split for q,k (+ plain split for v).
// Q pre-scaled by 0.125*log2(e): QK scores come out in log2 domain.
// ---------------------------------------------------------------------------
#define QSCALE 0.1803368801111204f   // 0.125 * log2(e)

__global__ void convert_kernel(const float* __restrict__ q,
                               const float* __restrict__ k,
                               const float* __restrict__ v,
                               const float* __restrict__ fc,
                               const float* __restrict__ fs,
                               __nv_bfloat16* __restrict__ qhi,
                               __nv_bfloat16* __restrict__ qlo,
                               __nv_bfloat16* __restrict__ khi,
                               __nv_bfloat16* __restrict__ klo,
                               __nv_bfloat16* __restrict__ vhi,
                               __nv_bfloat16* __restrict__ vlo) {
    int t = blockIdx.x * blockDim.x + threadIdx.x;
    const int total = B_ * S_ * D_ / 2;
    if (t >= total) return;
    int row = t >> 9;
    int cp = t & 511;
    int p = cp & 31;
    int s = row & (S_ - 1);
    float c = fc[s * 32 + p];
    float sn = fs[s * 32 + p];
    long base = (long)row * D_ + cp * 2;

    float2 qv = *(const float2*)(q + base);
    float qx = (qv.x * c - qv.y * sn) * QSCALE;
    float qy = (qv.x * sn + qv.y * c) * QSCALE;
    unsigned int hi, lo;
    split2(qx, qy, hi, lo);
    *(unsigned int*)(qhi + base) = hi;
    *(unsigned int*)(qlo + base) = lo;

    float2 kv = *(const float2*)(k + base);
    float kx = kv.x * c - kv.y * sn;
    float ky = kv.x * sn + kv.y * c;
    split2(kx, ky, hi, lo);
    *(unsigned int*)(khi + base) = hi;
    *(unsigned int*)(klo + base) = lo;

    float2 vv = *(const float2*)(v + base);
    split2(vv.x, vv.y, hi, lo);
    *(unsigned int*)(vhi + base) = hi;
    *(unsigned int*)(vlo + base) = lo;
}

// ---------------------------------------------------------------------------
// Flash attention: pre-split bf16 inputs, cp.async double-buffered K/V.
// 128 threads = 4 warps; warp w owns query rows [w*16, w*16+16).
// Output written pre-split (bf16 hi/lo) for the out-projection GEMM.
// ---------------------------------------------------------------------------
#define KP 72
#define TILE_E (64 * KP)
#define FLASH_SMEM (8 * TILE_E * 2)

__global__ __launch_bounds__(128) void flash2(const __nv_bfloat16* __restrict__ qhi,
                                              const __nv_bfloat16* __restrict__ qlo,
                                              const __nv_bfloat16* __restrict__ khi,
                                              const __nv_bfloat16* __restrict__ klo,
                                              const __nv_bfloat16* __restrict__ vhi,
                                              const __nv_bfloat16* __restrict__ vlo,
                                              __nv_bfloat16* __restrict__ ohi,
                                              __nv_bfloat16* __restrict__ olo) {
    extern __shared__ __nv_bfloat16 smB[];

    const int tid = threadIdx.x;
    const int lane = tid & 31;
    const int wid = tid >> 5;
    const int g = lane >> 2;
    const int t4 = lane & 3;
    const int wrow = wid * 16;
    const int grp = lane >> 3;
    const int rr  = lane & 7;

    const int qt = blockIdx.x;
    const int bh = blockIdx.y;
    const int q0 = qt * 64;

    const long headoff = (long)(bh >> 4) * S_ * D_ + (bh & 15) * HD_;
    const __nv_bfloat16* srcp[4] = {khi + headoff, klo + headoff,
                                    vhi + headoff, vlo + headoff};

    const unsigned int smbase = (unsigned int)__cvta_generic_to_shared(smB);

    unsigned int qh[4][4], ql[4][4];
    {
        const __nv_bfloat16* qhb = qhi + headoff;
        const __nv_bfloat16* qlb = qlo + headoff;
        const long r0 = (long)(q0 + wrow + g) * D_;
        const long r1 = (long)(q0 + wrow + g + 8) * D_;
#pragma unroll
        for (int kc = 0; kc < 4; kc++) {
            const int cb = kc * 16 + 2 * t4;
            qh[kc][0] = *(const unsigned int*)(qhb + r0 + cb);
            qh[kc][1] = *(const unsigned int*)(qhb + r1 + cb);
            qh[kc][2] = *(const unsigned int*)(qhb + r0 + cb + 8);
            qh[kc][3] = *(const unsigned int*)(qhb + r1 + cb + 8);
            ql[kc][0] = *(const unsigned int*)(qlb + r0 + cb);
            ql[kc][1] = *(const unsigned int*)(qlb + r1 + cb);
            ql[kc][2] = *(const unsigned int*)(qlb + r0 + cb + 8);
            ql[kc][3] = *(const unsigned int*)(qlb + r1 + cb + 8);
        }
    }

    auto issue = [&](int jt, int buf) {
        const int k0 = jt * 64;
#pragma unroll
        for (int i = 0; i < 16; i++) {
            const int G = tid + i * 128;
            const int arr = G >> 9;
            const int rem = G & 511;
            const int row = rem >> 3;
            const int ch = rem & 7;
            unsigned int dst = smbase +
                ((unsigned)((buf * 4 + arr) * TILE_E + row * KP + ch * 8)) * 2;
            cp_async16(dst, srcp[arr] + ((long)(k0 + row) * D_ + ch * 8));
        }
        cp_commit();
    };

    float oacc[8][4];
#pragma unroll
    for (int nt = 0; nt < 8; nt++)
#pragma unroll
        for (int r = 0; r < 4; r++) oacc[nt][r] = 0.f;
    float m0 = -1e30f, m1 = -1e30f, l0 = 0.f, l1 = 0.f;

    const int ntiles = qt + 1;
    issue(0, 0);

    for (int jt = 0; jt < ntiles; jt++) {
        const int buf = jt & 1;
        if (jt + 1 < ntiles) {
            issue(jt + 1, buf ^ 1);
            cp_wait<1>();
        } else {
            cp_wait<0>();
        }
        __syncthreads();

        const __nv_bfloat16* kh_s = smB + (buf * 4 + 0) * TILE_E;
        const __nv_bfloat16* kl_s = smB + (buf * 4 + 1) * TILE_E;
        const __nv_bfloat16* vh_s = smB + (buf * 4 + 2) * TILE_E;
        const __nv_bfloat16* vl_s = smB + (buf * 4 + 3) * TILE_E;

        float sc[8][4];
#pragma unroll
        for (int nt = 0; nt < 8; nt++)
#pragma unroll
            for (int r = 0; r < 4; r++) sc[nt][r] = 0.f;

#pragma unroll
        for (int dc = 0; dc < 4; dc++) {
#pragma unroll
            for (int np = 0; np < 4; np++) {
                const int ntA = 2 * np, ntB = 2 * np + 1;
                const int keysel = (grp & 2) ? ntB : ntA;
                const int colsel = dc * 16 + ((grp & 1) ? 8 : 0);
                unsigned int ahh = (unsigned int)__cvta_generic_to_shared(
                    kh_s + (keysel * 8 + rr) * KP + colsel);
                unsigned int ahl = (unsigned int)__cvta_generic_to_shared(
                    kl_s + (keysel * 8 + rr) * KP + colsel);
                unsigned int bhA[2], bhB[2], blA[2], blB[2];
                ldsm4(bhA[0], bhA[1], bhB[0], bhB[1], ahh);
                ldsm4(blA[0], blA[1], blB[0], blB[1], ahl);
                mma_bf16(sc[ntA], qh[dc], blA);
                mma_bf16(sc[ntA], ql[dc], bhA);
                mma_bf16(sc[ntA], qh[dc], bhA);
                mma_bf16(sc[ntB], qh[dc], blB);
                mma_bf16(sc[ntB], ql[dc], bhB);
                mma_bf16(sc[ntB], qh[dc], bhB);
            }
        }

        if (jt == qt) {
            const int r0l = wrow + g;
#pragma unroll
            for (int nt = 0; nt < 8; nt++) {
                const int c = nt * 8 + 2 * t4;
                if (c > r0l)          sc[nt][0] = -1e30f;
                if (c + 1 > r0l)      sc[nt][1] = -1e30f;
                if (c > r0l + 8)      sc[nt][2] = -1e30f;
                if (c + 1 > r0l + 8)  sc[nt][3] = -1e30f;
            }
        }

        float tm0 = -1e30f, tm1 = -1e30f;
#pragma unroll
        for (int nt = 0; nt < 8; nt++) {
            tm0 = fmaxf(tm0, fmaxf(sc[nt][0], sc[nt][1]));
            tm1 = fmaxf(tm1, fmaxf(sc[nt][2], sc[nt][3]));
        }
        tm0 = fmaxf(tm0, __shfl_xor_sync(0xffffffffu, tm0, 1));
        tm0 = fmaxf(tm0, __shfl_xor_sync(0xffffffffu, tm0, 2));
        tm1 = fmaxf(tm1, __shfl_xor_sync(0xffffffffu, tm1, 1));
        tm1 = fmaxf(tm1, __shfl_xor_sync(0xffffffffu, tm1, 2));

        float mn0 = fmaxf(m0, tm0);
        float mn1 = fmaxf(m1, tm1);
        float al0 = ex2f(m0 - mn0);
        float al1 = ex2f(m1 - mn1);
        m0 = mn0; m1 = mn1;

        float ps0 = 0.f, ps1 = 0.f;
#pragma unroll
        for (int nt = 0; nt < 8; nt++) {
            sc[nt][0] = ex2f(sc[nt][0] - m0);
            sc[nt][1] = ex2f(sc[nt][1] - m0);
            sc[nt][2] = ex2f(sc[nt][2] - m1);
            sc[nt][3] = ex2f(sc[nt][3] - m1);
            ps0 += sc[nt][0] + sc[nt][1];
            ps1 += sc[nt][2] + sc[nt][3];
        }
        ps0 += __shfl_xor_sync(0xffffffffu, ps0, 1);
        ps0 += __shfl_xor_sync(0xffffffffu, ps0, 2);
        ps1 += __shfl_xor_sync(0xffffffffu, ps1, 1);
        ps1 += __shfl_xor_sync(0xffffffffu, ps1, 2);
        l0 = l0 * al0 + ps0;
        l1 = l1 * al1 + ps1;

#pragma unroll
        for (int nt = 0; nt < 8; nt++) {
            oacc[nt][0] *= al0; oacc[nt][1] *= al0;
            oacc[nt][2] *= al1; oacc[nt][3] *= al1;
        }

#pragma unroll
        for (int kc = 0; kc < 4; kc++) {
            unsigned int ph[4], pl[4];
            split2(sc[2 * kc][0], sc[2 * kc][1], ph[0], pl[0]);
            split2(sc[2 * kc][2], sc[2 * kc][3], ph[1], pl[1]);
            split2(sc[2 * kc + 1][0], sc[2 * kc + 1][1], ph[2], pl[2]);
            split2(sc[2 * kc + 1][2], sc[2 * kc + 1][3], ph[3], pl[3]);
#pragma unroll
            for (int np = 0; np < 4; np++) {
                const int ntA = 2 * np, ntB = 2 * np + 1;
                const int rowsel = kc * 16 + ((grp & 1) ? 8 : 0) + rr;
                const int colsel = ((grp & 2) ? ntB : ntA) * 8;
                unsigned int avh = (unsigned int)__cvta_generic_to_shared(
                    vh_s + rowsel * KP + colsel);
                unsigned int avl = (unsigned int)__cvta_generic_to_shared(
                    vl_s + rowsel * KP + colsel);
                unsigned int vhA[2], vhB[2], vlA[2], vlB[2];
                ldsm4t(vhA[0], vhA[1], vhB[0], vhB[1], avh);
                ldsm4t(vlA[0], vlA[1], vlB[0], vlB[1], avl);
                mma_bf16(oacc[ntA], ph, vlA);
                mma_bf16(oacc[ntA], pl, vhA);
                mma_bf16(oacc[ntA], ph, vhA);
                mma_bf16(oacc[ntB], ph, vlB);
                mma_bf16(oacc[ntB], pl, vhB);
                mma_bf16(oacc[ntB], ph, vhB);
            }
        }
        __syncthreads();
    }

    // ---- Normalize, split, and write pre-split output ----
    const float inv0 = 1.f / l0;
    const float inv1 = 1.f / l1;
    const int row0 = q0 + wrow + g;
    __nv_bfloat16* ohb = ohi + headoff;
    __nv_bfloat16* olb = olo + headoff;
#pragma unroll
    for (int nt = 0; nt < 8; nt++) {
        const int col = nt * 8 + 2 * t4;
        unsigned int hi, lo;
        split2(oacc[nt][0] * inv0, oacc[nt][1] * inv0, hi, lo);
        *(unsigned int*)(ohb + (long)row0 * D_ + col) = hi;
        *(unsigned int*)(olb + (long)row0 * D_ + col) = lo;
        split2(oacc[nt][2] * inv1, oacc[nt][3] * inv1, hi, lo);
        *(unsigned int*)(ohb + (long)(row0 + 8) * D_ + col) = hi;
        *(unsigned int*)(olb + (long)(row0 + 8) * D_ + col) = lo;
    }
}

// ---------------------------------------------------------------------------
// Launch
// ---------------------------------------------------------------------------
extern "C" void kernel_launch(void* const* d_in, const int* in_sizes, int n_in,
                              void* d_out, int out_size) {
    const float* x  = (const float*)d_in[0];
    const float* wq = (const float*)d_in[1];
    const float* wk = (const float*)d_in[2];
    const float* wv = (const float*)d_in[3];
    const float* wo = (const float*)d_in[4];
    const float* fc = (const float*)d_in[5];
    const float* fs = (const float*)d_in[6];
    float* out = (float*)d_out;

    float *q, *k, *v;
    cudaGetSymbolAddress((void**)&q, g_q);
    cudaGetSymbolAddress((void**)&k, g_k);
    cudaGetSymbolAddress((void**)&v, g_v);
    __nv_bfloat16 *xhi, *xlo, *whi, *wlo;
    __nv_bfloat16 *qhi, *qlo, *khi, *klo, *vhi, *vlo, *ahi, *alo;
    cudaGetSymbolAddress((void**)&xhi, g_xhi);
    cudaGetSymbolAddress((void**)&xlo, g_xlo);
    cudaGetSymbolAddress((void**)&whi, g_whi);
    cudaGetSymbolAddress((void**)&wlo, g_wlo);
    cudaGetSymbolAddress((void**)&qhi, g_qhi);
    cudaGetSymbolAddress((void**)&qlo, g_qlo);
    cudaGetSymbolAddress((void**)&khi, g_khi);
    cudaGetSymbolAddress((void**)&klo, g_klo);
    cudaGetSymbolAddress((void**)&vhi, g_vhi);
    cudaGetSymbolAddress((void**)&vlo, g_vlo);
    cudaGetSymbolAddress((void**)&ahi, g_ahi);
    cudaGetSymbolAddress((void**)&alo, g_alo);

    // Pre-split x and all weights
    const int xpairs = M_ * D_ / 2;
    const int wpairs = D_ * D_ / 2;
    split_kernel<<<(xpairs + 255) / 256, 256>>>(x, xhi, xlo, xpairs);
    split_kernel<<<(wpairs + 255) / 256, 256>>>(wq, whi, wlo, wpairs);
    split_kernel<<<(wpairs + 255) / 256, 256>>>(wk, whi + (long)D_ * D_,
                                                wlo + (long)D_ * D_, wpairs);
    split_kernel<<<(wpairs + 255) / 256, 256>>>(wv, whi + 2L * D_ * D_,
                                                wlo + 2L * D_ * D_, wpairs);
    split_kernel<<<(wpairs + 255) / 256, 256>>>(wo, whi + 3L * D_ * D_,
                                                wlo + 3L * D_ * D_, wpairs);

    cudaFuncSetAttribute(qkv_gemm, cudaFuncAttributeMaxDynamicSharedMemorySize,
                         GEMM_SMEM);
    cudaFuncSetAttribute(out_gemm, cudaFuncAttributeMaxDynamicSharedMemorySize,
                         GEMM_SMEM);

    qkv_gemm<<<dim3(24, M_ / BM), 256, GEMM_SMEM>>>(xhi, xlo, whi, wlo, q, k, v);

    const int conv_total = B_ * S_ * D_ / 2;
    convert_kernel<<<(conv_total + 255) / 256, 256>>>(q, k, v, fc, fs,
                                                      qhi, qlo, khi, klo, vhi, vlo);

    cudaFuncSetAttribute(flash2, cudaFuncAttributeMaxDynamicSharedMemorySize,
                         FLASH_SMEM);
    flash2<<<dim3(S_ / 64, B_ * H_), 128, FLASH_SMEM>>>(qhi, qlo, khi, klo,
                                                        vhi, vlo, ahi, alo);

    out_gemm<<<dim3(D_ / BN, M_ / BM), 256, GEMM_SMEM>>>(ahi, alo, whi, wlo, out);
}